// round 1
// baseline (speedup 1.0000x reference)
#include <cuda_runtime.h>
#include <math.h>

#define BTCH 8
#define SEQ  2048
#define DIMD 128
#define NTOK (BTCH*SEQ)   /* 16384 */
#define WIN  64
#define NHEAD 8
#define HD   16
#define FFND 512

// ---------------- scratch (device globals; no runtime allocation) ----------------
__device__ float g_qkv [NTOK*384];
__device__ float g_attn[NTOK*DIMD];
__device__ float g_tmp [NTOK*DIMD];
__device__ float g_x1  [NTOK*DIMD];
__device__ float g_hbuf[NTOK*FFND];
__device__ float g_x2  [NTOK*DIMD];
__device__ float g_se  [NTOK*DIMD];
__device__ float g_te  [NTOK*DIMD];
__device__ float g_invs[NTOK];
__device__ float g_invt[NTOK];
__device__ float g_Mpart[32*BTCH*DIMD*DIMD];
__device__ float g_M   [BTCH*DIMD*DIMD];
__device__ float g_sim [NTOK];
__device__ float g_qi  [NTOK*DIMD];
__device__ float g_kvi [NTOK*256];
__device__ float g_ip  [NTOK*DIMD];

// ---------------- generic SGEMM: C[M,N] = A[M,K] @ W[N,K]^T + bias ----------------
// BM=BN=128, BK=8, 256 threads, 8x8 microtile. All dims multiples of tile sizes here.
// EPI: 0 = bias only, 1 = bias + exact-erf GELU, 2 = out = resid + scale[row]*(acc+bias)
template<int EPI>
__global__ void gemm128(const float* __restrict__ A, const float* __restrict__ W,
                        const float* __restrict__ bias, float* __restrict__ C,
                        int K, int N,
                        const float* __restrict__ resid, const float* __restrict__ scale)
{
    __shared__ float As[8][128];
    __shared__ float Bs[8][128];
    const int m0 = blockIdx.y * 128;
    const int n0 = blockIdx.x * 128;
    const int t  = threadIdx.x;
    const int ty = t >> 4, tx = t & 15;
    const int lr  = t >> 1;         // 0..127
    const int lk4 = (t & 1) * 4;    // 0 or 4

    float acc[8][8];
    #pragma unroll
    for (int q = 0; q < 8; q++)
        #pragma unroll
        for (int p = 0; p < 8; p++) acc[q][p] = 0.f;

    for (int k0 = 0; k0 < K; k0 += 8) {
        float4 av = *(const float4*)&A[(size_t)(m0 + lr) * K + k0 + lk4];
        float4 bv = *(const float4*)&W[(size_t)(n0 + lr) * K + k0 + lk4];
        As[lk4+0][lr] = av.x; As[lk4+1][lr] = av.y; As[lk4+2][lr] = av.z; As[lk4+3][lr] = av.w;
        Bs[lk4+0][lr] = bv.x; Bs[lk4+1][lr] = bv.y; Bs[lk4+2][lr] = bv.z; Bs[lk4+3][lr] = bv.w;
        __syncthreads();
        #pragma unroll
        for (int kk = 0; kk < 8; kk++) {
            float a[8], b[8];
            #pragma unroll
            for (int q = 0; q < 8; q++) { a[q] = As[kk][ty*8 + q]; b[q] = Bs[kk][tx*8 + q]; }
            #pragma unroll
            for (int q = 0; q < 8; q++)
                #pragma unroll
                for (int p = 0; p < 8; p++) acc[q][p] += a[q] * b[p];
        }
        __syncthreads();
    }

    #pragma unroll
    for (int q = 0; q < 8; q++) {
        int m = m0 + ty*8 + q;
        #pragma unroll
        for (int p = 0; p < 8; p++) {
            int n = n0 + tx*8 + p;
            float v = acc[q][p] + bias[n];
            if (EPI == 1) v = 0.5f * v * (1.f + erff(v * 0.70710678118654752f));
            if (EPI == 2) {
                C[(size_t)m * N + n] = resid[(size_t)m * N + n] + scale[m] * v;
            } else {
                C[(size_t)m * N + n] = v;
            }
        }
    }
}

// ---------------- residual + LayerNorm: out = LN(a+b)*g + beta ----------------
__global__ void ln_kernel(const float* __restrict__ a, const float* __restrict__ b,
                          const float* __restrict__ g, const float* __restrict__ beta,
                          float* __restrict__ out)
{
    int row = blockIdx.x;
    int t = threadIdx.x;   // 128
    float v = a[(size_t)row*128 + t] + b[(size_t)row*128 + t];
    __shared__ float red[4], red2[4];
    float s = v;
    #pragma unroll
    for (int o = 16; o > 0; o >>= 1) s += __shfl_xor_sync(0xffffffff, s, o);
    if ((t & 31) == 0) red[t >> 5] = s;
    __syncthreads();
    float mu = (red[0] + red[1] + red[2] + red[3]) * (1.f/128.f);
    float d = v - mu;
    float s2 = d * d;
    #pragma unroll
    for (int o = 16; o > 0; o >>= 1) s2 += __shfl_xor_sync(0xffffffff, s2, o);
    if ((t & 31) == 0) red2[t >> 5] = s2;
    __syncthreads();
    float var = (red2[0] + red2[1] + red2[2] + red2[3]) * (1.f/128.f);
    out[(size_t)row*128 + t] = d * rsqrtf(var + 1e-5f) * g[t] + beta[t];
}

// ---------------- local-window causal attention (64x64 windows, 8 heads of 16) ----
__global__ void winattn(const float* __restrict__ qkv, float* __restrict__ out)
{
    __shared__ float qs[WIN][HD], ks[WIN][HD], vs[WIN][HD], sc[WIN][WIN+1];
    const int base = blockIdx.x * WIN;
    const int t = threadIdx.x;   // 256
    for (int h = 0; h < NHEAD; h++) {
        for (int e = t; e < WIN*HD; e += 256) {
            int r = e >> 4, c = e & 15;
            size_t rb = (size_t)(base + r) * 384 + h*16 + c;
            qs[r][c] = qkv[rb];
            ks[r][c] = qkv[rb + 128];
            vs[r][c] = qkv[rb + 256];
        }
        __syncthreads();
        for (int e = t; e < WIN*WIN; e += 256) {
            int i = e >> 6, j = e & 63;
            float s = 0.f;
            #pragma unroll
            for (int d = 0; d < 16; d++) s += qs[i][d] * ks[j][d];
            sc[i][j] = s * 0.25f;
        }
        __syncthreads();
        if (t < WIN) {
            int i = t;
            float mx = -1e30f;
            for (int j = 0; j <= i; j++) mx = fmaxf(mx, sc[i][j]);
            float sum = 0.f;
            for (int j = 0; j <= i; j++) { float p = expf(sc[i][j] - mx); sc[i][j] = p; sum += p; }
            float inv = 1.f / sum;
            for (int j = 0; j <= i; j++) sc[i][j] *= inv;
            for (int j = i + 1; j < WIN; j++) sc[i][j] = 0.f;
        }
        __syncthreads();
        for (int e = t; e < WIN*HD; e += 256) {
            int i = e >> 4, d = e & 15;
            float s = 0.f;
            for (int j = 0; j < WIN; j++) s += sc[i][j] * vs[j][d];
            out[(size_t)(base + i) * 128 + h*16 + d] = s;
        }
        __syncthreads();
    }
}

// ---------------- per-row inverse L2 norm (cos-normalize) ----------------
__global__ void rownorm(const float* __restrict__ x, float* __restrict__ inv)
{
    int row = blockIdx.x * 8 + (threadIdx.x >> 5);
    int lane = threadIdx.x & 31;
    const float* p = x + (size_t)row * 128;
    float s = 0.f;
    #pragma unroll
    for (int c = 0; c < 4; c++) { float v = p[lane + c*32]; s += v * v; }
    #pragma unroll
    for (int o = 16; o > 0; o >>= 1) s += __shfl_xor_sync(0xffffffff, s, o);
    if (lane == 0) inv[row] = 1.f / fmaxf(sqrtf(s), 1e-8f);
}

// ---------------- M[b] = sn[b]^T @ tn[b]  (partials, deterministic) ----------------
__global__ void macc(const float* __restrict__ se, const float* __restrict__ te,
                     const float* __restrict__ invs, const float* __restrict__ invt,
                     float* __restrict__ Mpart)
{
    const int b = blockIdx.y, jc = blockIdx.x;      // 32 chunks of 64 j
    const int row0 = b * SEQ + jc * 64;
    __shared__ float sns[16][128], tns[16][128];
    const int t = threadIdx.x;
    const int ty = t >> 4, tx = t & 15;
    float c[8][8];
    #pragma unroll
    for (int q = 0; q < 8; q++)
        #pragma unroll
        for (int p = 0; p < 8; p++) c[q][p] = 0.f;

    for (int ch = 0; ch < 4; ch++) {
        int j0 = ch * 16;
        for (int idx = t; idx < 16*128; idx += 256) {
            int r = idx >> 7, cc = idx & 127;
            int row = row0 + j0 + r;
            sns[r][cc] = se[(size_t)row*128 + cc] * invs[row];
            tns[r][cc] = te[(size_t)row*128 + cc] * invt[row];
        }
        __syncthreads();
        #pragma unroll
        for (int jj = 0; jj < 16; jj++) {
            float a[8], bb[8];
            #pragma unroll
            for (int q = 0; q < 8; q++) { a[q] = sns[jj][ty*8 + q]; bb[q] = tns[jj][tx*8 + q]; }
            #pragma unroll
            for (int q = 0; q < 8; q++)
                #pragma unroll
                for (int p = 0; p < 8; p++) c[q][p] += a[q] * bb[p];
        }
        __syncthreads();
    }
    float* o = Mpart + (size_t)(jc * 8 + b) * (128*128);
    #pragma unroll
    for (int q = 0; q < 8; q++)
        #pragma unroll
        for (int p = 0; p < 8; p++)
            o[(ty*8 + q)*128 + tx*8 + p] = c[q][p];
}

__global__ void mreduce(const float* __restrict__ Mpart, float* __restrict__ M)
{
    int idx = blockIdx.x * 256 + threadIdx.x;   // 8*16384 total
    float s = 0.f;
    #pragma unroll
    for (int p = 0; p < 32; p++) s += Mpart[(size_t)p * (BTCH*128*128) + idx];
    M[idx] = s;
}

// ---------------- sim[b,i] = (1/S) * sn_i^T M[b] tn_i ----------------
__global__ void simk(const float* __restrict__ se, const float* __restrict__ te,
                     const float* __restrict__ invs, const float* __restrict__ invt,
                     const float* __restrict__ M, float* __restrict__ sim)
{
    extern __shared__ float Ms[];                 // 16384 floats
    __shared__ float sn[128], tn[128], red[8];
    const int b = blockIdx.y;
    const int t = threadIdx.x;                    // 256
    for (int idx = t; idx < 128*128; idx += 256) Ms[idx] = M[(size_t)b * 16384 + idx];
    __syncthreads();
    for (int r = 0; r < 64; r++) {
        int row = b * SEQ + blockIdx.x * 64 + r;
        if (t < 128) sn[t] = se[(size_t)row*128 + t] * invs[row];
        else         tn[t-128] = te[(size_t)row*128 + (t-128)] * invt[row];
        __syncthreads();
        float acc = 0.f;
        for (int idx = t; idx < 128*128; idx += 256)
            acc += sn[idx >> 7] * tn[idx & 127] * Ms[idx];
        #pragma unroll
        for (int o = 16; o > 0; o >>= 1) acc += __shfl_xor_sync(0xffffffff, acc, o);
        if ((t & 31) == 0) red[t >> 5] = acc;
        __syncthreads();
        if (t == 0) {
            float s = 0.f;
            #pragma unroll
            for (int w = 0; w < 8; w++) s += red[w];
            sim[row] = s * (1.f / (float)SEQ);
        }
        __syncthreads();
    }
}

// ------------- interaction attention: len=8 (batch axis), batch=S, 8 heads of 16 ----
__global__ void interattn(const float* __restrict__ qb, const float* __restrict__ kvb,
                          float* __restrict__ out)
{
    int gid = blockIdx.x * 256 + threadIdx.x;     // 2048*8*8 = 131072 threads
    int s = gid >> 6; int r = gid & 63; int h = r >> 3; int i = r & 7;
    const float* q = qb + ((size_t)i * SEQ + s) * 128 + h*16;
    float qr[16];
    #pragma unroll
    for (int d = 0; d < 16; d++) qr[d] = q[d];
    float sc[8];
    float mx = -1e30f;
    #pragma unroll
    for (int j = 0; j < 8; j++) {
        const float* k = kvb + ((size_t)j * SEQ + s) * 256 + h*16;
        float a = 0.f;
        #pragma unroll
        for (int d = 0; d < 16; d++) a += qr[d] * k[d];
        sc[j] = a * 0.25f;
        mx = fmaxf(mx, sc[j]);
    }
    float sum = 0.f;
    #pragma unroll
    for (int j = 0; j < 8; j++) { sc[j] = expf(sc[j] - mx); sum += sc[j]; }
    float inv = 1.f / sum;
    float o[16];
    #pragma unroll
    for (int d = 0; d < 16; d++) o[d] = 0.f;
    #pragma unroll
    for (int j = 0; j < 8; j++) {
        const float* v = kvb + ((size_t)j * SEQ + s) * 256 + 128 + h*16;
        float p = sc[j] * inv;
        #pragma unroll
        for (int d = 0; d < 16; d++) o[d] += p * v[d];
    }
    float* op = out + ((size_t)i * SEQ + s) * 128 + h*16;
    #pragma unroll
    for (int d = 0; d < 16; d++) op[d] = o[d];
}

// ==================================================================================
extern "C" void kernel_launch(void* const* d_in, const int* in_sizes, int n_in,
                              void* d_out, int out_size)
{
    const float* x        = (const float*)d_in[0];
    const float* spatial  = (const float*)d_in[1];
    const float* temporal = (const float*)d_in[2];
    const float* lw_in_w  = (const float*)d_in[3];
    const float* lw_in_b  = (const float*)d_in[4];
    const float* lw_out_w = (const float*)d_in[5];
    const float* lw_out_b = (const float*)d_in[6];
    const float* spat_w   = (const float*)d_in[7];
    const float* spat_b   = (const float*)d_in[8];
    const float* temp_w   = (const float*)d_in[9];
    const float* temp_b   = (const float*)d_in[10];
    const float* int_in_w = (const float*)d_in[11];
    const float* int_in_b = (const float*)d_in[12];
    const float* int_out_w= (const float*)d_in[13];
    const float* int_out_b= (const float*)d_in[14];
    const float* ffn_w1   = (const float*)d_in[15];
    const float* ffn_b1   = (const float*)d_in[16];
    const float* ffn_w2   = (const float*)d_in[17];
    const float* ffn_b2   = (const float*)d_in[18];
    const float* ln1_g    = (const float*)d_in[19];
    const float* ln1_b    = (const float*)d_in[20];
    const float* ln2_g    = (const float*)d_in[21];
    const float* ln2_b    = (const float*)d_in[22];
    float* out = (float*)d_out;

    void *p;
    cudaGetSymbolAddress(&p, g_qkv);  float* qkv  = (float*)p;
    cudaGetSymbolAddress(&p, g_attn); float* attn = (float*)p;
    cudaGetSymbolAddress(&p, g_tmp);  float* tmp  = (float*)p;
    cudaGetSymbolAddress(&p, g_x1);   float* x1   = (float*)p;
    cudaGetSymbolAddress(&p, g_hbuf); float* hbuf = (float*)p;
    cudaGetSymbolAddress(&p, g_x2);   float* x2   = (float*)p;
    cudaGetSymbolAddress(&p, g_se);   float* se   = (float*)p;
    cudaGetSymbolAddress(&p, g_te);   float* te   = (float*)p;
    cudaGetSymbolAddress(&p, g_invs); float* invs = (float*)p;
    cudaGetSymbolAddress(&p, g_invt); float* invt = (float*)p;
    cudaGetSymbolAddress(&p, g_Mpart);float* Mp   = (float*)p;
    cudaGetSymbolAddress(&p, g_M);    float* M    = (float*)p;
    cudaGetSymbolAddress(&p, g_sim);  float* sim  = (float*)p;
    cudaGetSymbolAddress(&p, g_qi);   float* qi   = (float*)p;
    cudaGetSymbolAddress(&p, g_kvi);  float* kvi  = (float*)p;
    cudaGetSymbolAddress(&p, g_ip);   float* ip   = (float*)p;

    cudaFuncSetAttribute(simk, cudaFuncAttributeMaxDynamicSharedMemorySize, 65536);

    // 1. local-window attention
    gemm128<0><<<dim3(3,128),256>>>(x, lw_in_w, lw_in_b, qkv, 128, 384, nullptr, nullptr);
    winattn<<<256,256>>>(qkv, attn);
    gemm128<0><<<dim3(1,128),256>>>(attn, lw_out_w, lw_out_b, tmp, 128, 128, nullptr, nullptr);
    ln_kernel<<<NTOK,128>>>(tmp, x, ln1_g, ln1_b, x1);

    // 2. FFN
    gemm128<1><<<dim3(4,128),256>>>(x1, ffn_w1, ffn_b1, hbuf, 128, 512, nullptr, nullptr);
    gemm128<0><<<dim3(1,128),256>>>(hbuf, ffn_w2, ffn_b2, tmp, 512, 128, nullptr, nullptr);
    ln_kernel<<<NTOK,128>>>(tmp, x1, ln2_g, ln2_b, x2);

    // 3. spatio-temporal embeddings + factorized similarity
    gemm128<0><<<dim3(1,128),256>>>(spatial,  spat_w, spat_b, se, 128, 128, nullptr, nullptr);
    gemm128<0><<<dim3(1,128),256>>>(temporal, temp_w, temp_b, te, 128, 128, nullptr, nullptr);
    rownorm<<<NTOK/8,256>>>(se, invs);
    rownorm<<<NTOK/8,256>>>(te, invt);
    macc<<<dim3(32,8),256>>>(se, te, invs, invt, Mp);
    mreduce<<<(BTCH*128*128)/256,256>>>(Mp, M);
    simk<<<dim3(32,8),256,65536>>>(se, te, invs, invt, M, sim);

    // 4. interaction attention (q from se, k/v from te)
    gemm128<0><<<dim3(1,128),256>>>(se, int_in_w, int_in_b, qi, 128, 128, nullptr, nullptr);
    gemm128<0><<<dim3(2,128),256>>>(te, int_in_w + 128*128, int_in_b + 128, kvi, 128, 256, nullptr, nullptr);
    interattn<<<512,256>>>(qi, kvi, ip);

    // 5. final: out = x2 + sim * (ip @ int_out_w^T + int_out_b)
    gemm128<2><<<dim3(1,128),256>>>(ip, int_out_w, int_out_b, out, 128, 128, x2, sim);
}

// round 6
// speedup vs baseline: 1.8202x; 1.8202x over previous
#include <cuda_runtime.h>
#include <math.h>
#include <stdint.h>

#define BTCH 8
#define SEQ  2048
#define DIMD 128
#define NTOK (BTCH*SEQ)   /* 16384 */
#define WIN  64
#define NHEAD 8
#define HD   16
#define FFND 512

// ---------------- scratch (device globals; no runtime allocation) ----------------
__device__ float g_qkv [NTOK*384];
__device__ float g_attn[NTOK*DIMD];
__device__ float g_tmp [NTOK*DIMD];
__device__ float g_x1  [NTOK*DIMD];
__device__ float g_hbuf[NTOK*FFND];
__device__ float g_x2  [NTOK*DIMD];
__device__ float g_se  [NTOK*DIMD];
__device__ float g_te  [NTOK*DIMD];
__device__ float g_invs[NTOK];
__device__ float g_invt[NTOK];
__device__ float g_Mpart[32*BTCH*DIMD*DIMD];
__device__ float g_M   [BTCH*DIMD*DIMD];
__device__ float g_sim [NTOK];
__device__ float g_qi  [NTOK*DIMD];
__device__ float g_kvi [NTOK*256];
__device__ float g_ip  [NTOK*DIMD];

// ---------------- tf32 helpers ----------------
__device__ __forceinline__ uint32_t f2tf32(float x) {
    uint32_t r;
    asm("cvt.rna.tf32.f32 %0, %1;" : "=r"(r) : "f"(x));
    return r;
}
__device__ __forceinline__ void mma_tf32(float c[4], const uint32_t a[4], const uint32_t b[2]) {
    asm("mma.sync.aligned.m16n8k8.row.col.f32.tf32.tf32.f32 "
        "{%0,%1,%2,%3}, {%4,%5,%6,%7}, {%8,%9}, {%0,%1,%2,%3};"
        : "+f"(c[0]), "+f"(c[1]), "+f"(c[2]), "+f"(c[3])
        : "r"(a[0]), "r"(a[1]), "r"(a[2]), "r"(a[3]), "r"(b[0]), "r"(b[1]));
}

// -------- tensor-core SGEMM (tf32): C[M,N] = A[M,K] @ W[N,K]^T + bias --------
// BM=128, BK=32, BN templated (128 or 64). 256 threads = 8 warps.
// BN=128: warps 2x4, warp tile 64x32.  BN=64: warps 4x2, warp tile 32x32.
// EPI: 0 = bias, 1 = bias + exact-erf GELU, 2 = resid + scale[row]*(acc+bias)
template<int BN, int EPI>
__global__ void gemm_tc(const float* __restrict__ A, const float* __restrict__ W,
                        const float* __restrict__ bias, float* __restrict__ C,
                        int K, int N,
                        const float* __restrict__ resid, const float* __restrict__ scale)
{
    constexpr int BM = 128, BK = 32;
    constexpr int WM = (BN == 128) ? 64 : 32;
    constexpr int WN = 32;
    constexpr int WCOLS = BN / WN;         // 4 or 2
    constexpr int MT = WM / 16;            // 4 or 2
    constexpr int NT = WN / 8;             // 4
    constexpr int LDS_ = BK + 4;           // 36: bank = (4*row+col)%32 -> permutation

    __shared__ uint32_t As[BM][LDS_];
    __shared__ uint32_t Bs[BN][LDS_];

    const int t = threadIdx.x;
    const int warp = t >> 5, lane = t & 31;
    const int wm = (warp / WCOLS) * WM;
    const int wn = (warp % WCOLS) * WN;
    const int g  = lane >> 2;     // 0..7
    const int tq = lane & 3;      // 0..3

    const int m0 = blockIdx.y * BM;
    const int n0 = blockIdx.x * BN;

    float acc[MT][NT][4];
    #pragma unroll
    for (int mi = 0; mi < MT; mi++)
        #pragma unroll
        for (int ni = 0; ni < NT; ni++)
            #pragma unroll
            for (int q = 0; q < 4; q++) acc[mi][ni][q] = 0.f;

    const int lr = t >> 3;          // 0..31
    const int lc = (t & 7) * 4;     // 0,4,...,28

    for (int k0 = 0; k0 < K; k0 += BK) {
        #pragma unroll
        for (int i = 0; i < 4; i++) {
            int r = lr + i * 32;
            float4 v = *(const float4*)&A[(size_t)(m0 + r) * K + k0 + lc];
            As[r][lc+0] = f2tf32(v.x); As[r][lc+1] = f2tf32(v.y);
            As[r][lc+2] = f2tf32(v.z); As[r][lc+3] = f2tf32(v.w);
        }
        #pragma unroll
        for (int i = 0; i < BN/32; i++) {
            int r = lr + i * 32;
            float4 v = *(const float4*)&W[(size_t)(n0 + r) * K + k0 + lc];
            Bs[r][lc+0] = f2tf32(v.x); Bs[r][lc+1] = f2tf32(v.y);
            Bs[r][lc+2] = f2tf32(v.z); Bs[r][lc+3] = f2tf32(v.w);
        }
        __syncthreads();

        #pragma unroll
        for (int kk = 0; kk < BK; kk += 8) {
            uint32_t af[MT][4], bf[NT][2];
            #pragma unroll
            for (int mi = 0; mi < MT; mi++) {
                int mr = wm + mi * 16;
                af[mi][0] = As[mr + g    ][kk + tq    ];
                af[mi][1] = As[mr + g + 8][kk + tq    ];
                af[mi][2] = As[mr + g    ][kk + tq + 4];
                af[mi][3] = As[mr + g + 8][kk + tq + 4];
            }
            #pragma unroll
            for (int ni = 0; ni < NT; ni++) {
                int nr = wn + ni * 8;
                bf[ni][0] = Bs[nr + g][kk + tq    ];
                bf[ni][1] = Bs[nr + g][kk + tq + 4];
            }
            #pragma unroll
            for (int mi = 0; mi < MT; mi++)
                #pragma unroll
                for (int ni = 0; ni < NT; ni++)
                    mma_tf32(acc[mi][ni], af[mi], bf[ni]);
        }
        __syncthreads();
    }

    // epilogue: c0:(m,nn) c1:(m,nn+1) c2:(m+8,nn) c3:(m+8,nn+1)
    #pragma unroll
    for (int mi = 0; mi < MT; mi++) {
        #pragma unroll
        for (int ni = 0; ni < NT; ni++) {
            int m = m0 + wm + mi * 16 + g;
            int nn = n0 + wn + ni * 8 + tq * 2;
            float b0 = bias[nn], b1 = bias[nn + 1];
            #pragma unroll
            for (int half = 0; half < 2; half++) {
                int mm = m + half * 8;
                float v0 = acc[mi][ni][half*2 + 0] + b0;
                float v1 = acc[mi][ni][half*2 + 1] + b1;
                if (EPI == 1) {
                    v0 = 0.5f * v0 * (1.f + erff(v0 * 0.70710678118654752f));
                    v1 = 0.5f * v1 * (1.f + erff(v1 * 0.70710678118654752f));
                }
                if (EPI == 2) {
                    float sc = scale[mm];
                    v0 = resid[(size_t)mm * N + nn    ] + sc * v0;
                    v1 = resid[(size_t)mm * N + nn + 1] + sc * v1;
                }
                *(float2*)&C[(size_t)mm * N + nn] = make_float2(v0, v1);
            }
        }
    }
}

// ---------------- residual + LayerNorm: out = LN(a+b)*g + beta ----------------
__global__ void ln_kernel(const float* __restrict__ a, const float* __restrict__ b,
                          const float* __restrict__ g, const float* __restrict__ beta,
                          float* __restrict__ out)
{
    int row = blockIdx.x;
    int t = threadIdx.x;   // 128
    float v = a[(size_t)row*128 + t] + b[(size_t)row*128 + t];
    __shared__ float red[4], red2[4];
    float s = v;
    #pragma unroll
    for (int o = 16; o > 0; o >>= 1) s += __shfl_xor_sync(0xffffffff, s, o);
    if ((t & 31) == 0) red[t >> 5] = s;
    __syncthreads();
    float mu = (red[0] + red[1] + red[2] + red[3]) * (1.f/128.f);
    float d = v - mu;
    float s2 = d * d;
    #pragma unroll
    for (int o = 16; o > 0; o >>= 1) s2 += __shfl_xor_sync(0xffffffff, s2, o);
    if ((t & 31) == 0) red2[t >> 5] = s2;
    __syncthreads();
    float var = (red2[0] + red2[1] + red2[2] + red2[3]) * (1.f/128.f);
    out[(size_t)row*128 + t] = d * rsqrtf(var + 1e-5f) * g[t] + beta[t];
}

// ---------------- local-window causal attention (64x64 windows, 8 heads of 16) ----
__global__ void winattn(const float* __restrict__ qkv, float* __restrict__ out)
{
    __shared__ float qs[WIN][HD], ks[WIN][HD], vs[WIN][HD], sc[WIN][WIN+1];
    const int base = blockIdx.x * WIN;
    const int t = threadIdx.x;   // 256
    for (int h = 0; h < NHEAD; h++) {
        for (int e = t; e < WIN*HD; e += 256) {
            int r = e >> 4, c = e & 15;
            size_t rb = (size_t)(base + r) * 384 + h*16 + c;
            qs[r][c] = qkv[rb];
            ks[r][c] = qkv[rb + 128];
            vs[r][c] = qkv[rb + 256];
        }
        __syncthreads();
        for (int e = t; e < WIN*WIN; e += 256) {
            int i = e >> 6, j = e & 63;
            float s = 0.f;
            #pragma unroll
            for (int d = 0; d < 16; d++) s += qs[i][d] * ks[j][d];
            sc[i][j] = s * 0.25f;
        }
        __syncthreads();
        if (t < WIN) {
            int i = t;
            float mx = -1e30f;
            for (int j = 0; j <= i; j++) mx = fmaxf(mx, sc[i][j]);
            float sum = 0.f;
            for (int j = 0; j <= i; j++) { float p = expf(sc[i][j] - mx); sc[i][j] = p; sum += p; }
            float inv = 1.f / sum;
            for (int j = 0; j <= i; j++) sc[i][j] *= inv;
            for (int j = i + 1; j < WIN; j++) sc[i][j] = 0.f;
        }
        __syncthreads();
        for (int e = t; e < WIN*HD; e += 256) {
            int i = e >> 4, d = e & 15;
            float s = 0.f;
            for (int j = 0; j < WIN; j++) s += sc[i][j] * vs[j][d];
            out[(size_t)(base + i) * 128 + h*16 + d] = s;
        }
        __syncthreads();
    }
}

// ---------------- per-row inverse L2 norm (cos-normalize) ----------------
__global__ void rownorm(const float* __restrict__ x, float* __restrict__ inv)
{
    int row = blockIdx.x * 8 + (threadIdx.x >> 5);
    int lane = threadIdx.x & 31;
    const float* p = x + (size_t)row * 128;
    float s = 0.f;
    #pragma unroll
    for (int c = 0; c < 4; c++) { float v = p[lane + c*32]; s += v * v; }
    #pragma unroll
    for (int o = 16; o > 0; o >>= 1) s += __shfl_xor_sync(0xffffffff, s, o);
    if (lane == 0) inv[row] = 1.f / fmaxf(sqrtf(s), 1e-8f);
}

// ---------------- M[b] = sn[b]^T @ tn[b]  (partials, deterministic) ----------------
__global__ void macc(const float* __restrict__ se, const float* __restrict__ te,
                     const float* __restrict__ invs, const float* __restrict__ invt,
                     float* __restrict__ Mpart)
{
    const int b = blockIdx.y, jc = blockIdx.x;      // 32 chunks of 64 j
    const int row0 = b * SEQ + jc * 64;
    __shared__ float sns[16][128], tns[16][128];
    const int t = threadIdx.x;
    const int ty = t >> 4, tx = t & 15;
    float c[8][8];
    #pragma unroll
    for (int q = 0; q < 8; q++)
        #pragma unroll
        for (int p = 0; p < 8; p++) c[q][p] = 0.f;

    for (int ch = 0; ch < 4; ch++) {
        int j0 = ch * 16;
        for (int idx = t; idx < 16*128; idx += 256) {
            int r = idx >> 7, cc = idx & 127;
            int row = row0 + j0 + r;
            sns[r][cc] = se[(size_t)row*128 + cc] * invs[row];
            tns[r][cc] = te[(size_t)row*128 + cc] * invt[row];
        }
        __syncthreads();
        #pragma unroll
        for (int jj = 0; jj < 16; jj++) {
            float a[8], bb[8];
            #pragma unroll
            for (int q = 0; q < 8; q++) { a[q] = sns[jj][ty*8 + q]; bb[q] = tns[jj][tx*8 + q]; }
            #pragma unroll
            for (int q = 0; q < 8; q++)
                #pragma unroll
                for (int p = 0; p < 8; p++) c[q][p] += a[q] * bb[p];
        }
        __syncthreads();
    }
    float* o = Mpart + (size_t)(jc * 8 + b) * (128*128);
    #pragma unroll
    for (int q = 0; q < 8; q++)
        #pragma unroll
        for (int p = 0; p < 8; p++)
            o[(ty*8 + q)*128 + tx*8 + p] = c[q][p];
}

__global__ void mreduce(const float* __restrict__ Mpart, float* __restrict__ M)
{
    int idx = blockIdx.x * 256 + threadIdx.x;   // 8*16384 total
    float s = 0.f;
    #pragma unroll
    for (int p = 0; p < 32; p++) s += Mpart[(size_t)p * (BTCH*128*128) + idx];
    M[idx] = s;
}

// ---------------- sim[b,i] = (1/S) * sn_i^T M[b] tn_i ----------------
__global__ void simk(const float* __restrict__ se, const float* __restrict__ te,
                     const float* __restrict__ invs, const float* __restrict__ invt,
                     const float* __restrict__ M, float* __restrict__ sim)
{
    extern __shared__ float Ms[];                 // 16384 floats
    __shared__ float sn[128], tn[128], red[8];
    const int b = blockIdx.y;
    const int t = threadIdx.x;                    // 256
    for (int idx = t; idx < 128*128; idx += 256) Ms[idx] = M[(size_t)b * 16384 + idx];
    __syncthreads();
    for (int r = 0; r < 64; r++) {
        int row = b * SEQ + blockIdx.x * 64 + r;
        if (t < 128) sn[t] = se[(size_t)row*128 + t] * invs[row];
        else         tn[t-128] = te[(size_t)row*128 + (t-128)] * invt[row];
        __syncthreads();
        float acc = 0.f;
        for (int idx = t; idx < 128*128; idx += 256)
            acc += sn[idx >> 7] * tn[idx & 127] * Ms[idx];
        #pragma unroll
        for (int o = 16; o > 0; o >>= 1) acc += __shfl_xor_sync(0xffffffff, acc, o);
        if ((t & 31) == 0) red[t >> 5] = acc;
        __syncthreads();
        if (t == 0) {
            float s = 0.f;
            #pragma unroll
            for (int w = 0; w < 8; w++) s += red[w];
            sim[row] = s * (1.f / (float)SEQ);
        }
        __syncthreads();
    }
}

// ------------- interaction attention: len=8 (batch axis), batch=S, 8 heads of 16 ----
__global__ void interattn(const float* __restrict__ qb, const float* __restrict__ kvb,
                          float* __restrict__ out)
{
    int gid = blockIdx.x * 256 + threadIdx.x;     // 2048*8*8 = 131072 threads
    int s = gid >> 6; int r = gid & 63; int h = r >> 3; int i = r & 7;
    const float* q = qb + ((size_t)i * SEQ + s) * 128 + h*16;
    float qr[16];
    #pragma unroll
    for (int d = 0; d < 16; d++) qr[d] = q[d];
    float sc[8];
    float mx = -1e30f;
    #pragma unroll
    for (int j = 0; j < 8; j++) {
        const float* k = kvb + ((size_t)j * SEQ + s) * 256 + h*16;
        float a = 0.f;
        #pragma unroll
        for (int d = 0; d < 16; d++) a += qr[d] * k[d];
        sc[j] = a * 0.25f;
        mx = fmaxf(mx, sc[j]);
    }
    float sum = 0.f;
    #pragma unroll
    for (int j = 0; j < 8; j++) { sc[j] = expf(sc[j] - mx); sum += sc[j]; }
    float inv = 1.f / sum;
    float o[16];
    #pragma unroll
    for (int d = 0; d < 16; d++) o[d] = 0.f;
    #pragma unroll
    for (int j = 0; j < 8; j++) {
        const float* v = kvb + ((size_t)j * SEQ + s) * 256 + 128 + h*16;
        float p = sc[j] * inv;
        #pragma unroll
        for (int d = 0; d < 16; d++) o[d] += p * v[d];
    }
    float* op = out + ((size_t)i * SEQ + s) * 128 + h*16;
    #pragma unroll
    for (int d = 0; d < 16; d++) op[d] = o[d];
}

// ==================================================================================
extern "C" void kernel_launch(void* const* d_in, const int* in_sizes, int n_in,
                              void* d_out, int out_size)
{
    const float* x        = (const float*)d_in[0];
    const float* spatial  = (const float*)d_in[1];
    const float* temporal = (const float*)d_in[2];
    const float* lw_in_w  = (const float*)d_in[3];
    const float* lw_in_b  = (const float*)d_in[4];
    const float* lw_out_w = (const float*)d_in[5];
    const float* lw_out_b = (const float*)d_in[6];
    const float* spat_w   = (const float*)d_in[7];
    const float* spat_b   = (const float*)d_in[8];
    const float* temp_w   = (const float*)d_in[9];
    const float* temp_b   = (const float*)d_in[10];
    const float* int_in_w = (const float*)d_in[11];
    const float* int_in_b = (const float*)d_in[12];
    const float* int_out_w= (const float*)d_in[13];
    const float* int_out_b= (const float*)d_in[14];
    const float* ffn_w1   = (const float*)d_in[15];
    const float* ffn_b1   = (const float*)d_in[16];
    const float* ffn_w2   = (const float*)d_in[17];
    const float* ffn_b2   = (const float*)d_in[18];
    const float* ln1_g    = (const float*)d_in[19];
    const float* ln1_b    = (const float*)d_in[20];
    const float* ln2_g    = (const float*)d_in[21];
    const float* ln2_b    = (const float*)d_in[22];
    float* out = (float*)d_out;

    void *p;
    cudaGetSymbolAddress(&p, g_qkv);  float* qkv  = (float*)p;
    cudaGetSymbolAddress(&p, g_attn); float* attn = (float*)p;
    cudaGetSymbolAddress(&p, g_tmp);  float* tmp  = (float*)p;
    cudaGetSymbolAddress(&p, g_x1);   float* x1   = (float*)p;
    cudaGetSymbolAddress(&p, g_hbuf); float* hbuf = (float*)p;
    cudaGetSymbolAddress(&p, g_x2);   float* x2   = (float*)p;
    cudaGetSymbolAddress(&p, g_se);   float* se   = (float*)p;
    cudaGetSymbolAddress(&p, g_te);   float* te   = (float*)p;
    cudaGetSymbolAddress(&p, g_invs); float* invs = (float*)p;
    cudaGetSymbolAddress(&p, g_invt); float* invt = (float*)p;
    cudaGetSymbolAddress(&p, g_Mpart);float* Mp   = (float*)p;
    cudaGetSymbolAddress(&p, g_M);    float* M    = (float*)p;
    cudaGetSymbolAddress(&p, g_sim);  float* sim  = (float*)p;
    cudaGetSymbolAddress(&p, g_qi);   float* qi   = (float*)p;
    cudaGetSymbolAddress(&p, g_kvi);  float* kvi  = (float*)p;
    cudaGetSymbolAddress(&p, g_ip);   float* ip   = (float*)p;

    cudaFuncSetAttribute(simk, cudaFuncAttributeMaxDynamicSharedMemorySize, 65536);

    // 1. local-window attention
    gemm_tc<128,0><<<dim3(3,128),256>>>(x, lw_in_w, lw_in_b, qkv, 128, 384, nullptr, nullptr);
    winattn<<<256,256>>>(qkv, attn);
    gemm_tc<64,0><<<dim3(2,128),256>>>(attn, lw_out_w, lw_out_b, tmp, 128, 128, nullptr, nullptr);
    ln_kernel<<<NTOK,128>>>(tmp, x, ln1_g, ln1_b, x1);

    // 2. FFN
    gemm_tc<128,1><<<dim3(4,128),256>>>(x1, ffn_w1, ffn_b1, hbuf, 128, 512, nullptr, nullptr);
    gemm_tc<64,0><<<dim3(2,128),256>>>(hbuf, ffn_w2, ffn_b2, tmp, 512, 128, nullptr, nullptr);
    ln_kernel<<<NTOK,128>>>(tmp, x1, ln2_g, ln2_b, x2);

    // 3. spatio-temporal embeddings + factorized similarity
    gemm_tc<64,0><<<dim3(2,128),256>>>(spatial,  spat_w, spat_b, se, 128, 128, nullptr, nullptr);
    gemm_tc<64,0><<<dim3(2,128),256>>>(temporal, temp_w, temp_b, te, 128, 128, nullptr, nullptr);
    rownorm<<<NTOK/8,256>>>(se, invs);
    rownorm<<<NTOK/8,256>>>(te, invt);
    macc<<<dim3(32,8),256>>>(se, te, invs, invt, Mp);
    mreduce<<<(BTCH*128*128)/256,256>>>(Mp, M);
    simk<<<dim3(32,8),256,65536>>>(se, te, invs, invt, M, sim);

    // 4. interaction attention (q from se, k/v from te)
    gemm_tc<64,0><<<dim3(2,128),256>>>(se, int_in_w, int_in_b, qi, 128, 128, nullptr, nullptr);
    gemm_tc<128,0><<<dim3(2,128),256>>>(te, int_in_w + 128*128, int_in_b + 128, kvi, 128, 256, nullptr, nullptr);
    interattn<<<512,256>>>(qi, kvi, ip);

    // 5. final: out = x2 + sim * (ip @ int_out_w^T + int_out_b)
    gemm_tc<64,2><<<dim3(2,128),256>>>(ip, int_out_w, int_out_b, out, 128, 128, x2, sim);
}

// round 9
// speedup vs baseline: 2.7931x; 1.5345x over previous
#include <cuda_runtime.h>
#include <math.h>
#include <stdint.h>

#define BTCH 8
#define SEQ  2048
#define DIMD 128
#define NTOK (BTCH*SEQ)   /* 16384 */
#define WIN  64
#define NHEAD 8
#define HD   16
#define FFND 512

// ---------------- scratch (device globals; no runtime allocation) ----------------
__device__ float g_qkv [NTOK*384];   // also reused: sn = [0:NTOK*128), tn = [NTOK*128:NTOK*256)
__device__ float g_attn[NTOK*DIMD];
__device__ float g_tmp [NTOK*DIMD];  // pre-ln buffers, later v = M@tn
__device__ float g_x1  [NTOK*DIMD];
__device__ float g_hbuf[NTOK*FFND];
__device__ float g_x2  [NTOK*DIMD];
__device__ float g_se  [NTOK*DIMD];
__device__ float g_te  [NTOK*DIMD];
__device__ float g_Mpart[16*BTCH*DIMD*DIMD];
__device__ float g_M   [BTCH*DIMD*DIMD];
__device__ float g_sim [NTOK];
__device__ float g_qi  [NTOK*DIMD];
__device__ float g_kvi [NTOK*256];
__device__ float g_ip  [NTOK*DIMD];
__device__ float g_xr  [NTOK*DIMD];  // tf32-rounded inputs
__device__ float g_spr [NTOK*DIMD];
__device__ float g_tpr [NTOK*DIMD];
__device__ float g_wts [294912];     // tf32-rounded weights, concatenated

// weight offsets inside g_wts
#define W_LWIN  0
#define W_LWOUT 49152
#define W_SPAT  65536
#define W_TEMP  81920
#define W_ININ  98304
#define W_INOUT 147456
#define W_FFN1  163840
#define W_FFN2  229376

// ---------------- tf32 helpers ----------------
__device__ __forceinline__ float rtf(float x) {
    uint32_t r;
    asm("cvt.rna.tf32.f32 %0, %1;" : "=r"(r) : "f"(x));
    return __uint_as_float(r);
}
__device__ __forceinline__ void mma_tf32(float c[4], const uint32_t a[4], const uint32_t b[2]) {
    asm("mma.sync.aligned.m16n8k8.row.col.f32.tf32.tf32.f32 "
        "{%0,%1,%2,%3}, {%4,%5,%6,%7}, {%8,%9}, {%0,%1,%2,%3};"
        : "+f"(c[0]), "+f"(c[1]), "+f"(c[2]), "+f"(c[3])
        : "r"(a[0]), "r"(a[1]), "r"(a[2]), "r"(a[3]), "r"(b[0]), "r"(b[1]));
}
__device__ __forceinline__ void cpasync16(uint32_t saddr, const float* g) {
    asm volatile("cp.async.cg.shared.global [%0], [%1], 16;\n" :: "r"(saddr), "l"(g));
}

// ---------------- pre-round inputs & weights to tf32 (rna) ----------------
struct RoundArgs {
    const float* src[12];
    float*       dst[12];
    int          len[12];
};
__global__ void roundmany(RoundArgs a)
{
    int seg = blockIdx.y;
    const float* s = a.src[seg];
    float* d = a.dst[seg];
    int n = a.len[seg];
    for (int i = blockIdx.x * 256 + threadIdx.x; i < n; i += gridDim.x * 256)
        d[i] = rtf(s[i]);
}

// -------- tensor-core GEMM (tf32, cp.async 2-stage): C = A[M,K] @ W[N,K]^T --------
// BM=128, BK=32, BN in {128,64}. 256 threads = 8 warps.
// EPI: 0 bias (+round), 1 bias+GELU (+round), 2 resid+scale (final, raw), 3 none (raw)
// BATCHW: W advances by 128*128 per 2048 A-rows (per-batch matrix)
template<int BN, int EPI, bool BATCHW>
__global__ void gemm_tc2(const float* __restrict__ A, const float* __restrict__ W,
                         const float* __restrict__ bias, float* __restrict__ C,
                         int K, int N,
                         const float* __restrict__ resid, const float* __restrict__ scale)
{
    constexpr int BM = 128, BK = 32;
    constexpr int WM = (BN == 128) ? 64 : 32;
    constexpr int WN = 32;
    constexpr int WCOLS = BN / WN;
    constexpr int MT = WM / 16;
    constexpr int NT = WN / 8;
    constexpr int LDS_ = 36;                 // bank = (4*row+col)%32 -> permutation
    constexpr int STG  = (BM + BN) * LDS_;   // words per stage

    extern __shared__ uint32_t sh[];
    const int t = threadIdx.x;
    const int warp = t >> 5, lane = t & 31;
    const int wm = (warp / WCOLS) * WM;
    const int wn = (warp % WCOLS) * WN;
    const int g  = lane >> 2;
    const int tq = lane & 3;
    const int m0 = blockIdx.y * BM;
    const int n0 = blockIdx.x * BN;
    const float* Wb = BATCHW ? (W + (size_t)(blockIdx.y >> 4) * 16384) : W;

    const uint32_t sbase = (uint32_t)__cvta_generic_to_shared(sh);
    const int lr = t >> 3;          // 0..31
    const int lc = (t & 7) * 4;     // 0..28

    auto load_stage = [&](int k0, int s) {
        uint32_t off = sbase + (uint32_t)s * STG * 4;
        #pragma unroll
        for (int i = 0; i < 4; i++) {
            int r = lr + 32 * i;
            cpasync16(off + (uint32_t)(r * LDS_ + lc) * 4, A + (size_t)(m0 + r) * K + k0 + lc);
        }
        uint32_t offB = off + (uint32_t)BM * LDS_ * 4;
        #pragma unroll
        for (int i = 0; i < BN / 32; i++) {
            int r = lr + 32 * i;
            cpasync16(offB + (uint32_t)(r * LDS_ + lc) * 4, Wb + (size_t)(n0 + r) * K + k0 + lc);
        }
        asm volatile("cp.async.commit_group;\n" ::);
    };

    float acc[MT][NT][4];
    #pragma unroll
    for (int mi = 0; mi < MT; mi++)
        #pragma unroll
        for (int ni = 0; ni < NT; ni++)
            #pragma unroll
            for (int q = 0; q < 4; q++) acc[mi][ni][q] = 0.f;

    load_stage(0, 0);
    const int KT = K / BK;
    for (int kt = 0; kt < KT; kt++) {
        if (kt + 1 < KT) {
            load_stage((kt + 1) * BK, (kt + 1) & 1);
            asm volatile("cp.async.wait_group 1;\n" ::);
        } else {
            asm volatile("cp.async.wait_group 0;\n" ::);
        }
        __syncthreads();
        const uint32_t (*As)[LDS_] = (const uint32_t(*)[LDS_])(sh + (kt & 1) * STG);
        const uint32_t (*Bs)[LDS_] = (const uint32_t(*)[LDS_])(sh + (kt & 1) * STG + BM * LDS_);
        #pragma unroll
        for (int kk = 0; kk < BK; kk += 8) {
            uint32_t af[MT][4], bf[NT][2];
            #pragma unroll
            for (int mi = 0; mi < MT; mi++) {
                int mr = wm + mi * 16;
                af[mi][0] = As[mr + g    ][kk + tq    ];
                af[mi][1] = As[mr + g + 8][kk + tq    ];
                af[mi][2] = As[mr + g    ][kk + tq + 4];
                af[mi][3] = As[mr + g + 8][kk + tq + 4];
            }
            #pragma unroll
            for (int ni = 0; ni < NT; ni++) {
                int nr = wn + ni * 8;
                bf[ni][0] = Bs[nr + g][kk + tq    ];
                bf[ni][1] = Bs[nr + g][kk + tq + 4];
            }
            #pragma unroll
            for (int mi = 0; mi < MT; mi++)
                #pragma unroll
                for (int ni = 0; ni < NT; ni++)
                    mma_tf32(acc[mi][ni], af[mi], bf[ni]);
        }
        __syncthreads();
    }

    #pragma unroll
    for (int mi = 0; mi < MT; mi++) {
        #pragma unroll
        for (int ni = 0; ni < NT; ni++) {
            int m = m0 + wm + mi * 16 + g;
            int nn = n0 + wn + ni * 8 + tq * 2;
            float b0 = 0.f, b1 = 0.f;
            if (EPI != 3) { b0 = bias[nn]; b1 = bias[nn + 1]; }
            #pragma unroll
            for (int half = 0; half < 2; half++) {
                int mm = m + half * 8;
                float v0 = acc[mi][ni][half*2 + 0] + b0;
                float v1 = acc[mi][ni][half*2 + 1] + b1;
                if (EPI == 1) {
                    v0 = 0.5f * v0 * (1.f + erff(v0 * 0.70710678118654752f));
                    v1 = 0.5f * v1 * (1.f + erff(v1 * 0.70710678118654752f));
                }
                if (EPI == 2) {
                    float sc = scale[mm];
                    v0 = resid[(size_t)mm * N + nn    ] + sc * v0;
                    v1 = resid[(size_t)mm * N + nn + 1] + sc * v1;
                }
                if (EPI == 0 || EPI == 1) { v0 = rtf(v0); v1 = rtf(v1); }
                *(float2*)&C[(size_t)mm * N + nn] = make_float2(v0, v1);
            }
        }
    }
}

// ---------------- residual + LayerNorm: out = LN(a+b)*g + beta ----------------
template<bool RND>
__global__ void ln_kernel(const float* __restrict__ a, const float* __restrict__ b,
                          const float* __restrict__ g, const float* __restrict__ beta,
                          float* __restrict__ out)
{
    int row = blockIdx.x;
    int t = threadIdx.x;   // 128
    float v = a[(size_t)row*128 + t] + b[(size_t)row*128 + t];
    __shared__ float red[4], red2[4];
    float s = v;
    #pragma unroll
    for (int o = 16; o > 0; o >>= 1) s += __shfl_xor_sync(0xffffffff, s, o);
    if ((t & 31) == 0) red[t >> 5] = s;
    __syncthreads();
    float mu = (red[0] + red[1] + red[2] + red[3]) * (1.f/128.f);
    float d = v - mu;
    float s2 = d * d;
    #pragma unroll
    for (int o = 16; o > 0; o >>= 1) s2 += __shfl_xor_sync(0xffffffff, s2, o);
    if ((t & 31) == 0) red2[t >> 5] = s2;
    __syncthreads();
    float var = (red2[0] + red2[1] + red2[2] + red2[3]) * (1.f/128.f);
    float r = d * rsqrtf(var + 1e-5f) * g[t] + beta[t];
    out[(size_t)row*128 + t] = RND ? rtf(r) : r;
}

// ------- local-window causal attention: one block per (window, head) -------
__global__ void winattn2(const float* __restrict__ qkv, float* __restrict__ out)
{
    __shared__ float qs[WIN][17], ks[WIN][17], vs[WIN][17], sc[WIN][65];
    const int w = blockIdx.x >> 3, h = blockIdx.x & 7;
    const int base = w * WIN;
    const int t = threadIdx.x;   // 128
    #pragma unroll
    for (int i = 0; i < 8; i++) {
        int idx = t + 128*i; int r = idx >> 4, c = idx & 15;
        size_t rb = (size_t)(base + r) * 384 + h*16 + c;
        qs[r][c] = qkv[rb];
        ks[r][c] = qkv[rb + 128];
        vs[r][c] = qkv[rb + 256];
    }
    __syncthreads();
    #pragma unroll
    for (int i = 0; i < 32; i++) {
        int idx = t + 128*i; int row = idx >> 6, j = idx & 63;
        float s = 0.f;
        #pragma unroll
        for (int d = 0; d < 16; d++) s += qs[row][d] * ks[j][d];
        sc[row][j] = s * 0.25f;
    }
    __syncthreads();
    if (t < 64) {
        int i = t;
        float mx = -1e30f;
        for (int j = 0; j <= i; j++) mx = fmaxf(mx, sc[i][j]);
        float sum = 0.f;
        for (int j = 0; j <= i; j++) { float p = expf(sc[i][j] - mx); sc[i][j] = p; sum += p; }
        float inv = 1.f / sum;
        for (int j = 0; j <= i; j++) sc[i][j] *= inv;
        for (int j = i + 1; j < 64; j++) sc[i][j] = 0.f;
    }
    __syncthreads();
    #pragma unroll
    for (int i2 = 0; i2 < 8; i2++) {
        int idx = t + 128*i2; int i = idx >> 4, d = idx & 15;
        float s = 0.f;
        for (int j = 0; j < 64; j++) s += sc[i][j] * vs[j][d];
        out[(size_t)(base + i) * 128 + h*16 + d] = rtf(s);
    }
}

// ------- cos-normalize: out = rtf(x / max(||x||,eps)), materialized -------
__global__ void normscale(const float* __restrict__ x, float* __restrict__ out)
{
    int row = blockIdx.x * 8 + (threadIdx.x >> 5);
    int lane = threadIdx.x & 31;
    const float* p = x + (size_t)row * 128;
    float v[4];
    float s = 0.f;
    #pragma unroll
    for (int c = 0; c < 4; c++) { v[c] = p[lane + c*32]; s += v[c] * v[c]; }
    #pragma unroll
    for (int o = 16; o > 0; o >>= 1) s += __shfl_xor_sync(0xffffffff, s, o);
    float inv = 1.f / fmaxf(sqrtf(s), 1e-8f);
    float* q = out + (size_t)row * 128;
    #pragma unroll
    for (int c = 0; c < 4; c++) q[lane + c*32] = rtf(v[c] * inv);
}

// ------- M partials via tensor cores: Mpart[p,b] = sn_chunk^T @ tn_chunk -------
// grid (16, 8): p = row chunk of 128, b = batch. 256 threads, warps 2x4.
// Tiles are [32 k-rows][128 dim-cols], pad to 136: 136%32==8 -> fragment bank
// = (8*tq+g)%32, a perfect permutation (conflict-free).
__global__ void macc_tc(const float* __restrict__ sn, const float* __restrict__ tn,
                        float* __restrict__ Mpart)
{
    constexpr int LDSm = 136;
    __shared__ uint32_t sns[32][LDSm], tns[32][LDSm];
    const int t = threadIdx.x;
    const int warp = t >> 5, lane = t & 31;
    const int wm = (warp >> 2) * 64, wn = (warp & 3) * 32;
    const int g = lane >> 2, tq = lane & 3;
    const size_t row0 = (size_t)blockIdx.y * SEQ + blockIdx.x * 128;

    float acc[4][4][4];
    #pragma unroll
    for (int mi = 0; mi < 4; mi++)
        #pragma unroll
        for (int ni = 0; ni < 4; ni++)
            #pragma unroll
            for (int q = 0; q < 4; q++) acc[mi][ni][q] = 0.f;

    for (int c0 = 0; c0 < 128; c0 += 32) {
        #pragma unroll
        for (int i = 0; i < 4; i++) {
            int idx = t + 256*i; int r = idx >> 5; int c4 = (idx & 31) * 4;
            float4 a = *(const float4*)&sn[(row0 + c0 + r) * 128 + c4];
            float4 b = *(const float4*)&tn[(row0 + c0 + r) * 128 + c4];
            *(float4*)&sns[r][c4] = a;
            *(float4*)&tns[r][c4] = b;
        }
        __syncthreads();
        #pragma unroll
        for (int kk = 0; kk < 32; kk += 8) {
            uint32_t af[4][4], bf[4][2];
            #pragma unroll
            for (int mi = 0; mi < 4; mi++) {
                int m = wm + mi * 16;
                af[mi][0] = sns[kk + tq    ][m + g    ];
                af[mi][1] = sns[kk + tq    ][m + g + 8];
                af[mi][2] = sns[kk + tq + 4][m + g    ];
                af[mi][3] = sns[kk + tq + 4][m + g + 8];
            }
            #pragma unroll
            for (int ni = 0; ni < 4; ni++) {
                int n = wn + ni * 8 + g;
                bf[ni][0] = tns[kk + tq    ][n];
                bf[ni][1] = tns[kk + tq + 4][n];
            }
            #pragma unroll
            for (int mi = 0; mi < 4; mi++)
                #pragma unroll
                for (int ni = 0; ni < 4; ni++)
                    mma_tf32(acc[mi][ni], af[mi], bf[ni]);
        }
        __syncthreads();
    }
    float* o = Mpart + ((size_t)blockIdx.x * BTCH + blockIdx.y) * 16384;
    #pragma unroll
    for (int mi = 0; mi < 4; mi++) {
        #pragma unroll
        for (int ni = 0; ni < 4; ni++) {
            int m = wm + mi * 16 + g;
            int nn = wn + ni * 8 + tq * 2;
            o[m*128 + nn]       = acc[mi][ni][0];
            o[m*128 + nn + 1]   = acc[mi][ni][1];
            o[(m+8)*128 + nn]   = acc[mi][ni][2];
            o[(m+8)*128 + nn+1] = acc[mi][ni][3];
        }
    }
}

__global__ void mreduce(const float* __restrict__ Mpart, float* __restrict__ M)
{
    int idx = blockIdx.x * 256 + threadIdx.x;   // 8*16384 total
    float s = 0.f;
    #pragma unroll
    for (int p = 0; p < 16; p++) s += Mpart[(size_t)p * (BTCH*128*128) + idx];
    M[idx] = rtf(s);
}

// ------- sim[row] = (sn[row] . v[row]) / SEQ -------
__global__ void simdot(const float* __restrict__ sn, const float* __restrict__ v,
                       float* __restrict__ sim)
{
    int row = blockIdx.x * 8 + (threadIdx.x >> 5);
    int lane = threadIdx.x & 31;
    const float* a = sn + (size_t)row * 128;
    const float* b = v  + (size_t)row * 128;
    float s = 0.f;
    #pragma unroll
    for (int c = 0; c < 4; c++) s += a[lane + c*32] * b[lane + c*32];
    #pragma unroll
    for (int o = 16; o > 0; o >>= 1) s += __shfl_xor_sync(0xffffffff, s, o);
    if (lane == 0) sim[row] = s * (1.f / (float)SEQ);
}

// ------- interaction attention: len=8 (batch axis), batch=S, 8 heads of 16 -------
__global__ void interattn(const float* __restrict__ qb, const float* __restrict__ kvb,
                          float* __restrict__ out)
{
    int gid = blockIdx.x * 256 + threadIdx.x;     // 2048*8*8 = 131072 threads
    int s = gid >> 6; int r = gid & 63; int h = r >> 3; int i = r & 7;
    const float* q = qb + ((size_t)i * SEQ + s) * 128 + h*16;
    float qr[16];
    #pragma unroll
    for (int d = 0; d < 16; d++) qr[d] = q[d];
    float sc[8];
    float mx = -1e30f;
    #pragma unroll
    for (int j = 0; j < 8; j++) {
        const float* k = kvb + ((size_t)j * SEQ + s) * 256 + h*16;
        float a = 0.f;
        #pragma unroll
        for (int d = 0; d < 16; d++) a += qr[d] * k[d];
        sc[j] = a * 0.25f;
        mx = fmaxf(mx, sc[j]);
    }
    float sum = 0.f;
    #pragma unroll
    for (int j = 0; j < 8; j++) { sc[j] = expf(sc[j] - mx); sum += sc[j]; }
    float inv = 1.f / sum;
    float o[16];
    #pragma unroll
    for (int d = 0; d < 16; d++) o[d] = 0.f;
    #pragma unroll
    for (int j = 0; j < 8; j++) {
        const float* v = kvb + ((size_t)j * SEQ + s) * 256 + 128 + h*16;
        float p = sc[j] * inv;
        #pragma unroll
        for (int d = 0; d < 16; d++) o[d] += p * v[d];
    }
    float* op = out + ((size_t)i * SEQ + s) * 128 + h*16;
    #pragma unroll
    for (int d = 0; d < 16; d++) op[d] = rtf(o[d]);
}

// ==================================================================================
extern "C" void kernel_launch(void* const* d_in, const int* in_sizes, int n_in,
                              void* d_out, int out_size)
{
    const float* x        = (const float*)d_in[0];
    const float* spatial  = (const float*)d_in[1];
    const float* temporal = (const float*)d_in[2];
    const float* lw_in_w  = (const float*)d_in[3];
    const float* lw_in_b  = (const float*)d_in[4];
    const float* lw_out_w = (const float*)d_in[5];
    const float* lw_out_b = (const float*)d_in[6];
    const float* spat_w   = (const float*)d_in[7];
    const float* spat_b   = (const float*)d_in[8];
    const float* temp_w   = (const float*)d_in[9];
    const float* temp_b   = (const float*)d_in[10];
    const float* int_in_w = (const float*)d_in[11];
    const float* int_in_b = (const float*)d_in[12];
    const float* int_out_w= (const float*)d_in[13];
    const float* int_out_b= (const float*)d_in[14];
    const float* ffn_w1   = (const float*)d_in[15];
    const float* ffn_b1   = (const float*)d_in[16];
    const float* ffn_w2   = (const float*)d_in[17];
    const float* ffn_b2   = (const float*)d_in[18];
    const float* ln1_g    = (const float*)d_in[19];
    const float* ln1_b    = (const float*)d_in[20];
    const float* ln2_g    = (const float*)d_in[21];
    const float* ln2_b    = (const float*)d_in[22];
    float* out = (float*)d_out;

    void *p;
    cudaGetSymbolAddress(&p, g_qkv);  float* qkv  = (float*)p;
    float* sn = qkv;                  // reuse after winattn
    float* tn = qkv + (size_t)NTOK*128;
    cudaGetSymbolAddress(&p, g_attn); float* attn = (float*)p;
    cudaGetSymbolAddress(&p, g_tmp);  float* tmp  = (float*)p;
    cudaGetSymbolAddress(&p, g_x1);   float* x1   = (float*)p;
    cudaGetSymbolAddress(&p, g_hbuf); float* hbuf = (float*)p;
    cudaGetSymbolAddress(&p, g_x2);   float* x2   = (float*)p;
    cudaGetSymbolAddress(&p, g_se);   float* se   = (float*)p;
    cudaGetSymbolAddress(&p, g_te);   float* te   = (float*)p;
    cudaGetSymbolAddress(&p, g_Mpart);float* Mp   = (float*)p;
    cudaGetSymbolAddress(&p, g_M);    float* M    = (float*)p;
    cudaGetSymbolAddress(&p, g_sim);  float* sim  = (float*)p;
    cudaGetSymbolAddress(&p, g_qi);   float* qi   = (float*)p;
    cudaGetSymbolAddress(&p, g_kvi);  float* kvi  = (float*)p;
    cudaGetSymbolAddress(&p, g_ip);   float* ip   = (float*)p;
    cudaGetSymbolAddress(&p, g_xr);   float* xr   = (float*)p;
    cudaGetSymbolAddress(&p, g_spr);  float* spr  = (float*)p;
    cudaGetSymbolAddress(&p, g_tpr);  float* tpr  = (float*)p;
    cudaGetSymbolAddress(&p, g_wts);  float* wts  = (float*)p;

    const int SM128 = 2 * (128 + 128) * 36 * 4;   // 73728
    const int SM64  = 2 * (128 +  64) * 36 * 4;   // 55296
    cudaFuncSetAttribute(gemm_tc2<128,0,false>, cudaFuncAttributeMaxDynamicSharedMemorySize, SM128);
    cudaFuncSetAttribute(gemm_tc2<128,1,false>, cudaFuncAttributeMaxDynamicSharedMemorySize, SM128);
    cudaFuncSetAttribute(gemm_tc2<64,0,false>,  cudaFuncAttributeMaxDynamicSharedMemorySize, SM64);
    cudaFuncSetAttribute(gemm_tc2<64,2,false>,  cudaFuncAttributeMaxDynamicSharedMemorySize, SM64);
    cudaFuncSetAttribute(gemm_tc2<64,3,true>,   cudaFuncAttributeMaxDynamicSharedMemorySize, SM64);

    // 0. pre-round all mma operands coming from harness inputs
    RoundArgs ra;
    ra.src[0] = x;        ra.dst[0] = xr;            ra.len[0] = NTOK*128;
    ra.src[1] = spatial;  ra.dst[1] = spr;           ra.len[1] = NTOK*128;
    ra.src[2] = temporal; ra.dst[2] = tpr;           ra.len[2] = NTOK*128;
    ra.src[3] = lw_in_w;  ra.dst[3] = wts + W_LWIN;  ra.len[3] = 384*128;
    ra.src[4] = lw_out_w; ra.dst[4] = wts + W_LWOUT; ra.len[4] = 128*128;
    ra.src[5] = spat_w;   ra.dst[5] = wts + W_SPAT;  ra.len[5] = 128*128;
    ra.src[6] = temp_w;   ra.dst[6] = wts + W_TEMP;  ra.len[6] = 128*128;
    ra.src[7] = int_in_w; ra.dst[7] = wts + W_ININ;  ra.len[7] = 384*128;
    ra.src[8] = int_out_w;ra.dst[8] = wts + W_INOUT; ra.len[8] = 128*128;
    ra.src[9] = ffn_w1;   ra.dst[9] = wts + W_FFN1;  ra.len[9] = 512*128;
    ra.src[10]= ffn_w2;   ra.dst[10]= wts + W_FFN2;  ra.len[10]= 128*512;
    ra.src[11]= ffn_w2;   ra.dst[11]= wts + W_FFN2;  ra.len[11]= 0;
    roundmany<<<dim3(1024,11),256>>>(ra);

    // 1. local-window attention
    gemm_tc2<128,0,false><<<dim3(3,128),256,SM128>>>(xr, wts + W_LWIN, lw_in_b, qkv, 128, 384, nullptr, nullptr);
    winattn2<<<2048,128>>>(qkv, attn);
    gemm_tc2<64,0,false><<<dim3(2,128),256,SM64>>>(attn, wts + W_LWOUT, lw_out_b, tmp, 128, 128, nullptr, nullptr);
    ln_kernel<true><<<NTOK,128>>>(tmp, x, ln1_g, ln1_b, x1);

    // 2. FFN
    gemm_tc2<128,1,false><<<dim3(4,128),256,SM128>>>(x1, wts + W_FFN1, ffn_b1, hbuf, 128, 512, nullptr, nullptr);
    gemm_tc2<64,0,false><<<dim3(2,128),256,SM64>>>(hbuf, wts + W_FFN2, ffn_b2, tmp, 512, 128, nullptr, nullptr);
    ln_kernel<false><<<NTOK,128>>>(tmp, x1, ln2_g, ln2_b, x2);

    // 3. spatio-temporal embeddings + factorized similarity
    gemm_tc2<64,0,false><<<dim3(2,128),256,SM64>>>(spr, wts + W_SPAT, spat_b, se, 128, 128, nullptr, nullptr);
    gemm_tc2<64,0,false><<<dim3(2,128),256,SM64>>>(tpr, wts + W_TEMP, temp_b, te, 128, 128, nullptr, nullptr);
    normscale<<<NTOK/8,256>>>(se, sn);
    normscale<<<NTOK/8,256>>>(te, tn);
    macc_tc<<<dim3(16,8),256>>>(sn, tn, Mp);
    mreduce<<<(BTCH*128*128)/256,256>>>(Mp, M);
    // v = tn @ M[b]^T  (per-batch W), then sim = (sn.v)/SEQ
    gemm_tc2<64,3,true><<<dim3(2,128),256,SM64>>>(tn, M, nullptr, tmp, 128, 128, nullptr, nullptr);
    simdot<<<NTOK/8,256>>>(sn, tmp, sim);

    // 4. interaction attention (q from se, k/v from te)
    gemm_tc2<64,0,false><<<dim3(2,128),256,SM64>>>(se, wts + W_ININ, int_in_b, qi, 128, 128, nullptr, nullptr);
    gemm_tc2<128,0,false><<<dim3(2,128),256,SM128>>>(te, wts + W_ININ + 128*128, int_in_b + 128, kvi, 128, 256, nullptr, nullptr);
    interattn<<<512,256>>>(qi, kvi, ip);

    // 5. final: out = x2 + sim * (ip @ int_out_w^T + int_out_b)
    gemm_tc2<64,2,false><<<dim3(2,128),256,SM64>>>(ip, wts + W_INOUT, int_out_b, out, 128, 128, x2, sim);
}

// round 10
// speedup vs baseline: 3.3100x; 1.1851x over previous
#include <cuda_runtime.h>
#include <math.h>
#include <stdint.h>

#define BTCH 8
#define SEQ  2048
#define DIMD 128
#define NTOK (BTCH*SEQ)   /* 16384 */
#define WIN  64
#define NHEAD 8
#define HD   16
#define FFND 512

// ---------------- scratch (device globals; no runtime allocation) ----------------
__device__ float g_qkv [NTOK*384];
__device__ float g_attn[NTOK*DIMD];
__device__ float g_tmp [NTOK*DIMD];   // main-path pre-LN buffer
__device__ float g_x1  [NTOK*DIMD];
__device__ float g_hbuf[NTOK*FFND];
__device__ float g_x2  [NTOK*DIMD];
__device__ float g_se  [NTOK*DIMD];
__device__ float g_te  [NTOK*DIMD];
__device__ float g_sn  [NTOK*DIMD];
__device__ float g_tn  [NTOK*DIMD];
__device__ float g_v   [NTOK*DIMD];   // v = tn @ M^T (ST path only)
__device__ float g_Mpart[16*BTCH*DIMD*DIMD];
__device__ float g_M   [BTCH*DIMD*DIMD];
__device__ float g_sim [NTOK];
__device__ float g_qi  [NTOK*DIMD];
__device__ float g_kvi [NTOK*256];
__device__ float g_ip  [NTOK*DIMD];

// ---------------- stream fork resources (created pre-main, before harness
// memory checkpoints; no device allocation inside kernel_launch) ----------------
static cudaStream_t g_s2;
static cudaEvent_t  g_e0, g_e1;
struct StreamInit {
    StreamInit() {
        cudaStreamCreateWithFlags(&g_s2, cudaStreamNonBlocking);
        cudaEventCreateWithFlags(&g_e0, cudaEventDisableTiming);
        cudaEventCreateWithFlags(&g_e1, cudaEventDisableTiming);
    }
};
static StreamInit g_si;

// ---------------- tf32 helpers ----------------
__device__ __forceinline__ uint32_t rtfb(uint32_t raw) {   // fp32 bits -> rna tf32 bits
    uint32_t r;
    asm("cvt.rna.tf32.f32 %0, %1;" : "=r"(r) : "f"(__uint_as_float(raw)));
    return r;
}
__device__ __forceinline__ void mma_tf32(float c[4], const uint32_t a[4], const uint32_t b[2]) {
    asm("mma.sync.aligned.m16n8k8.row.col.f32.tf32.tf32.f32 "
        "{%0,%1,%2,%3}, {%4,%5,%6,%7}, {%8,%9}, {%0,%1,%2,%3};"
        : "+f"(c[0]), "+f"(c[1]), "+f"(c[2]), "+f"(c[3])
        : "r"(a[0]), "r"(a[1]), "r"(a[2]), "r"(a[3]), "r"(b[0]), "r"(b[1]));
}
__device__ __forceinline__ void cpasync16(uint32_t saddr, const float* g) {
    asm volatile("cp.async.cg.shared.global [%0], [%1], 16;\n" :: "r"(saddr), "l"(g));
}

// -------- tensor-core GEMM (tf32, cp.async 2-stage): C = A[M,K] @ W[N,K]^T --------
// Raw fp32 in gmem/smem; cvt.rna.tf32 applied at fragment load (== pre-rounding).
// EPI: 0 bias, 1 bias+GELU, 2 resid + scale[row]*(acc+bias), 3 none
// BATCHW: W advances by 128*128 per 2048 A-rows
template<int BN, int EPI, bool BATCHW>
__global__ void gemm_tc2(const float* __restrict__ A, const float* __restrict__ W,
                         const float* __restrict__ bias, float* __restrict__ C,
                         int K, int N,
                         const float* __restrict__ resid, const float* __restrict__ scale)
{
    constexpr int BM = 128, BK = 32;
    constexpr int WM = (BN == 128) ? 64 : 32;
    constexpr int WN = 32;
    constexpr int WCOLS = BN / WN;
    constexpr int MT = WM / 16;
    constexpr int NT = WN / 8;
    constexpr int LDS_ = 36;                 // bank = (4*row+col)%32 -> permutation
    constexpr int STG  = (BM + BN) * LDS_;   // words per stage

    extern __shared__ uint32_t sh[];
    const int t = threadIdx.x;
    const int warp = t >> 5, lane = t & 31;
    const int wm = (warp / WCOLS) * WM;
    const int wn = (warp % WCOLS) * WN;
    const int g  = lane >> 2;
    const int tq = lane & 3;
    const int m0 = blockIdx.y * BM;
    const int n0 = blockIdx.x * BN;
    const float* Wb = BATCHW ? (W + (size_t)(blockIdx.y >> 4) * 16384) : W;

    const uint32_t sbase = (uint32_t)__cvta_generic_to_shared(sh);
    const int lr = t >> 3;          // 0..31
    const int lc = (t & 7) * 4;     // 0..28

    auto load_stage = [&](int k0, int s) {
        uint32_t off = sbase + (uint32_t)s * STG * 4;
        #pragma unroll
        for (int i = 0; i < 4; i++) {
            int r = lr + 32 * i;
            cpasync16(off + (uint32_t)(r * LDS_ + lc) * 4, A + (size_t)(m0 + r) * K + k0 + lc);
        }
        uint32_t offB = off + (uint32_t)BM * LDS_ * 4;
        #pragma unroll
        for (int i = 0; i < BN / 32; i++) {
            int r = lr + 32 * i;
            cpasync16(offB + (uint32_t)(r * LDS_ + lc) * 4, Wb + (size_t)(n0 + r) * K + k0 + lc);
        }
        asm volatile("cp.async.commit_group;\n" ::);
    };

    float acc[MT][NT][4];
    #pragma unroll
    for (int mi = 0; mi < MT; mi++)
        #pragma unroll
        for (int ni = 0; ni < NT; ni++)
            #pragma unroll
            for (int q = 0; q < 4; q++) acc[mi][ni][q] = 0.f;

    load_stage(0, 0);
    const int KT = K / BK;
    for (int kt = 0; kt < KT; kt++) {
        if (kt + 1 < KT) {
            load_stage((kt + 1) * BK, (kt + 1) & 1);
            asm volatile("cp.async.wait_group 1;\n" ::);
        } else {
            asm volatile("cp.async.wait_group 0;\n" ::);
        }
        __syncthreads();
        const uint32_t (*As)[LDS_] = (const uint32_t(*)[LDS_])(sh + (kt & 1) * STG);
        const uint32_t (*Bs)[LDS_] = (const uint32_t(*)[LDS_])(sh + (kt & 1) * STG + BM * LDS_);
        #pragma unroll
        for (int kk = 0; kk < BK; kk += 8) {
            uint32_t af[MT][4], bf[NT][2];
            #pragma unroll
            for (int mi = 0; mi < MT; mi++) {
                int mr = wm + mi * 16;
                af[mi][0] = rtfb(As[mr + g    ][kk + tq    ]);
                af[mi][1] = rtfb(As[mr + g + 8][kk + tq    ]);
                af[mi][2] = rtfb(As[mr + g    ][kk + tq + 4]);
                af[mi][3] = rtfb(As[mr + g + 8][kk + tq + 4]);
            }
            #pragma unroll
            for (int ni = 0; ni < NT; ni++) {
                int nr = wn + ni * 8;
                bf[ni][0] = rtfb(Bs[nr + g][kk + tq    ]);
                bf[ni][1] = rtfb(Bs[nr + g][kk + tq + 4]);
            }
            #pragma unroll
            for (int mi = 0; mi < MT; mi++)
                #pragma unroll
                for (int ni = 0; ni < NT; ni++)
                    mma_tf32(acc[mi][ni], af[mi], bf[ni]);
        }
        __syncthreads();
    }

    #pragma unroll
    for (int mi = 0; mi < MT; mi++) {
        #pragma unroll
        for (int ni = 0; ni < NT; ni++) {
            int m = m0 + wm + mi * 16 + g;
            int nn = n0 + wn + ni * 8 + tq * 2;
            float b0 = 0.f, b1 = 0.f;
            if (EPI != 3) { b0 = bias[nn]; b1 = bias[nn + 1]; }
            #pragma unroll
            for (int half = 0; half < 2; half++) {
                int mm = m + half * 8;
                float v0 = acc[mi][ni][half*2 + 0] + b0;
                float v1 = acc[mi][ni][half*2 + 1] + b1;
                if (EPI == 1) {
                    v0 = 0.5f * v0 * (1.f + erff(v0 * 0.70710678118654752f));
                    v1 = 0.5f * v1 * (1.f + erff(v1 * 0.70710678118654752f));
                }
                if (EPI == 2) {
                    float sc = scale[mm];
                    v0 = resid[(size_t)mm * N + nn    ] + sc * v0;
                    v1 = resid[(size_t)mm * N + nn + 1] + sc * v1;
                }
                *(float2*)&C[(size_t)mm * N + nn] = make_float2(v0, v1);
            }
        }
    }
}

// ---------------- residual + LayerNorm: out = LN(a+b)*g + beta ----------------
__global__ void ln_kernel(const float* __restrict__ a, const float* __restrict__ b,
                          const float* __restrict__ g, const float* __restrict__ beta,
                          float* __restrict__ out)
{
    int row = blockIdx.x;
    int t = threadIdx.x;   // 128
    float v = a[(size_t)row*128 + t] + b[(size_t)row*128 + t];
    __shared__ float red[4], red2[4];
    float s = v;
    #pragma unroll
    for (int o = 16; o > 0; o >>= 1) s += __shfl_xor_sync(0xffffffff, s, o);
    if ((t & 31) == 0) red[t >> 5] = s;
    __syncthreads();
    float mu = (red[0] + red[1] + red[2] + red[3]) * (1.f/128.f);
    float d = v - mu;
    float s2 = d * d;
    #pragma unroll
    for (int o = 16; o > 0; o >>= 1) s2 += __shfl_xor_sync(0xffffffff, s2, o);
    if ((t & 31) == 0) red2[t >> 5] = s2;
    __syncthreads();
    float var = (red2[0] + red2[1] + red2[2] + red2[3]) * (1.f/128.f);
    out[(size_t)row*128 + t] = d * rsqrtf(var + 1e-5f) * g[t] + beta[t];
}

// ------- local-window causal attention: one block per (window, head) -------
__global__ void winattn2(const float* __restrict__ qkv, float* __restrict__ out)
{
    __shared__ float qs[WIN][17], ks[WIN][17], vs[WIN][17], sc[WIN][65];
    const int w = blockIdx.x >> 3, h = blockIdx.x & 7;
    const int base = w * WIN;
    const int t = threadIdx.x;   // 128
    #pragma unroll
    for (int i = 0; i < 8; i++) {
        int idx = t + 128*i; int r = idx >> 4, c = idx & 15;
        size_t rb = (size_t)(base + r) * 384 + h*16 + c;
        qs[r][c] = qkv[rb];
        ks[r][c] = qkv[rb + 128];
        vs[r][c] = qkv[rb + 256];
    }
    __syncthreads();
    #pragma unroll
    for (int i = 0; i < 32; i++) {
        int idx = t + 128*i; int row = idx >> 6, j = idx & 63;
        float s = 0.f;
        #pragma unroll
        for (int d = 0; d < 16; d++) s += qs[row][d] * ks[j][d];
        sc[row][j] = s * 0.25f;
    }
    __syncthreads();
    if (t < 64) {
        int i = t;
        float mx = -1e30f;
        for (int j = 0; j <= i; j++) mx = fmaxf(mx, sc[i][j]);
        float sum = 0.f;
        for (int j = 0; j <= i; j++) { float p = expf(sc[i][j] - mx); sc[i][j] = p; sum += p; }
        float inv = 1.f / sum;
        for (int j = 0; j <= i; j++) sc[i][j] *= inv;
        for (int j = i + 1; j < 64; j++) sc[i][j] = 0.f;
    }
    __syncthreads();
    #pragma unroll
    for (int i2 = 0; i2 < 8; i2++) {
        int idx = t + 128*i2; int i = idx >> 4, d = idx & 15;
        float s = 0.f;
        for (int j = 0; j < 64; j++) s += sc[i][j] * vs[j][d];
        out[(size_t)(base + i) * 128 + h*16 + d] = s;
    }
}

// ------- cos-normalize both se->sn and te->tn (grid.y selects) -------
__global__ void normscale2(const float* __restrict__ se, const float* __restrict__ te,
                           float* __restrict__ sn, float* __restrict__ tn)
{
    const float* x   = blockIdx.y ? te : se;
    float*       out = blockIdx.y ? tn : sn;
    int row = blockIdx.x * 8 + (threadIdx.x >> 5);
    int lane = threadIdx.x & 31;
    const float* p = x + (size_t)row * 128;
    float v[4];
    float s = 0.f;
    #pragma unroll
    for (int c = 0; c < 4; c++) { v[c] = p[lane + c*32]; s += v[c] * v[c]; }
    #pragma unroll
    for (int o = 16; o > 0; o >>= 1) s += __shfl_xor_sync(0xffffffff, s, o);
    float inv = 1.f / fmaxf(sqrtf(s), 1e-8f);
    float* q = out + (size_t)row * 128;
    #pragma unroll
    for (int c = 0; c < 4; c++) q[lane + c*32] = v[c] * inv;
}

// ------- M partials via tensor cores: Mpart[p,b] = sn_chunk^T @ tn_chunk -------
// Tiles [32 k-rows][128 cols], pad 136 (136%32==8 -> conflict-free fragment banks).
__global__ void macc_tc(const float* __restrict__ sn, const float* __restrict__ tn,
                        float* __restrict__ Mpart)
{
    constexpr int LDSm = 136;
    __shared__ uint32_t sns[32][LDSm], tns[32][LDSm];
    const int t = threadIdx.x;
    const int warp = t >> 5, lane = t & 31;
    const int wm = (warp >> 2) * 64, wn = (warp & 3) * 32;
    const int g = lane >> 2, tq = lane & 3;
    const size_t row0 = (size_t)blockIdx.y * SEQ + blockIdx.x * 128;

    float acc[4][4][4];
    #pragma unroll
    for (int mi = 0; mi < 4; mi++)
        #pragma unroll
        for (int ni = 0; ni < 4; ni++)
            #pragma unroll
            for (int q = 0; q < 4; q++) acc[mi][ni][q] = 0.f;

    for (int c0 = 0; c0 < 128; c0 += 32) {
        #pragma unroll
        for (int i = 0; i < 4; i++) {
            int idx = t + 256*i; int r = idx >> 5; int c4 = (idx & 31) * 4;
            float4 a = *(const float4*)&sn[(row0 + c0 + r) * 128 + c4];
            float4 b = *(const float4*)&tn[(row0 + c0 + r) * 128 + c4];
            *(float4*)&sns[r][c4] = a;
            *(float4*)&tns[r][c4] = b;
        }
        __syncthreads();
        #pragma unroll
        for (int kk = 0; kk < 32; kk += 8) {
            uint32_t af[4][4], bf[4][2];
            #pragma unroll
            for (int mi = 0; mi < 4; mi++) {
                int m = wm + mi * 16;
                af[mi][0] = rtfb(sns[kk + tq    ][m + g    ]);
                af[mi][1] = rtfb(sns[kk + tq    ][m + g + 8]);
                af[mi][2] = rtfb(sns[kk + tq + 4][m + g    ]);
                af[mi][3] = rtfb(sns[kk + tq + 4][m + g + 8]);
            }
            #pragma unroll
            for (int ni = 0; ni < 4; ni++) {
                int n = wn + ni * 8 + g;
                bf[ni][0] = rtfb(tns[kk + tq    ][n]);
                bf[ni][1] = rtfb(tns[kk + tq + 4][n]);
            }
            #pragma unroll
            for (int mi = 0; mi < 4; mi++)
                #pragma unroll
                for (int ni = 0; ni < 4; ni++)
                    mma_tf32(acc[mi][ni], af[mi], bf[ni]);
        }
        __syncthreads();
    }
    float* o = Mpart + ((size_t)blockIdx.x * BTCH + blockIdx.y) * 16384;
    #pragma unroll
    for (int mi = 0; mi < 4; mi++) {
        #pragma unroll
        for (int ni = 0; ni < 4; ni++) {
            int m = wm + mi * 16 + g;
            int nn = wn + ni * 8 + tq * 2;
            o[m*128 + nn]       = acc[mi][ni][0];
            o[m*128 + nn + 1]   = acc[mi][ni][1];
            o[(m+8)*128 + nn]   = acc[mi][ni][2];
            o[(m+8)*128 + nn+1] = acc[mi][ni][3];
        }
    }
}

__global__ void mreduce(const float* __restrict__ Mpart, float* __restrict__ M)
{
    int idx = blockIdx.x * 256 + threadIdx.x;   // 8*16384 total
    float s = 0.f;
    #pragma unroll
    for (int p = 0; p < 16; p++) s += Mpart[(size_t)p * (BTCH*128*128) + idx];
    M[idx] = s;
}

// ------- sim[row] = (sn[row] . v[row]) / SEQ -------
__global__ void simdot(const float* __restrict__ sn, const float* __restrict__ v,
                       float* __restrict__ sim)
{
    int row = blockIdx.x * 8 + (threadIdx.x >> 5);
    int lane = threadIdx.x & 31;
    const float* a = sn + (size_t)row * 128;
    const float* b = v  + (size_t)row * 128;
    float s = 0.f;
    #pragma unroll
    for (int c = 0; c < 4; c++) s += a[lane + c*32] * b[lane + c*32];
    #pragma unroll
    for (int o = 16; o > 0; o >>= 1) s += __shfl_xor_sync(0xffffffff, s, o);
    if (lane == 0) sim[row] = s * (1.f / (float)SEQ);
}

// ------- interaction attention: len=8 (batch axis), batch=S, 8 heads of 16 -------
__global__ void interattn(const float* __restrict__ qb, const float* __restrict__ kvb,
                          float* __restrict__ out)
{
    int gid = blockIdx.x * 256 + threadIdx.x;     // 2048*8*8 = 131072 threads
    int s = gid >> 6; int r = gid & 63; int h = r >> 3; int i = r & 7;
    const float* q = qb + ((size_t)i * SEQ + s) * 128 + h*16;
    float qr[16];
    #pragma unroll
    for (int d = 0; d < 16; d++) qr[d] = q[d];
    float sc[8];
    float mx = -1e30f;
    #pragma unroll
    for (int j = 0; j < 8; j++) {
        const float* k = kvb + ((size_t)j * SEQ + s) * 256 + h*16;
        float a = 0.f;
        #pragma unroll
        for (int d = 0; d < 16; d++) a += qr[d] * k[d];
        sc[j] = a * 0.25f;
        mx = fmaxf(mx, sc[j]);
    }
    float sum = 0.f;
    #pragma unroll
    for (int j = 0; j < 8; j++) { sc[j] = expf(sc[j] - mx); sum += sc[j]; }
    float inv = 1.f / sum;
    float o[16];
    #pragma unroll
    for (int d = 0; d < 16; d++) o[d] = 0.f;
    #pragma unroll
    for (int j = 0; j < 8; j++) {
        const float* v = kvb + ((size_t)j * SEQ + s) * 256 + 128 + h*16;
        float p = sc[j] * inv;
        #pragma unroll
        for (int d = 0; d < 16; d++) o[d] += p * v[d];
    }
    float* op = out + ((size_t)i * SEQ + s) * 128 + h*16;
    #pragma unroll
    for (int d = 0; d < 16; d++) op[d] = o[d];
}

// ==================================================================================
extern "C" void kernel_launch(void* const* d_in, const int* in_sizes, int n_in,
                              void* d_out, int out_size)
{
    const float* x        = (const float*)d_in[0];
    const float* spatial  = (const float*)d_in[1];
    const float* temporal = (const float*)d_in[2];
    const float* lw_in_w  = (const float*)d_in[3];
    const float* lw_in_b  = (const float*)d_in[4];
    const float* lw_out_w = (const float*)d_in[5];
    const float* lw_out_b = (const float*)d_in[6];
    const float* spat_w   = (const float*)d_in[7];
    const float* spat_b   = (const float*)d_in[8];
    const float* temp_w   = (const float*)d_in[9];
    const float* temp_b   = (const float*)d_in[10];
    const float* int_in_w = (const float*)d_in[11];
    const float* int_in_b = (const float*)d_in[12];
    const float* int_out_w= (const float*)d_in[13];
    const float* int_out_b= (const float*)d_in[14];
    const float* ffn_w1   = (const float*)d_in[15];
    const float* ffn_b1   = (const float*)d_in[16];
    const float* ffn_w2   = (const float*)d_in[17];
    const float* ffn_b2   = (const float*)d_in[18];
    const float* ln1_g    = (const float*)d_in[19];
    const float* ln1_b    = (const float*)d_in[20];
    const float* ln2_g    = (const float*)d_in[21];
    const float* ln2_b    = (const float*)d_in[22];
    float* out = (float*)d_out;

    void *p;
    cudaGetSymbolAddress(&p, g_qkv);  float* qkv  = (float*)p;
    cudaGetSymbolAddress(&p, g_attn); float* attn = (float*)p;
    cudaGetSymbolAddress(&p, g_tmp);  float* tmp  = (float*)p;
    cudaGetSymbolAddress(&p, g_x1);   float* x1   = (float*)p;
    cudaGetSymbolAddress(&p, g_hbuf); float* hbuf = (float*)p;
    cudaGetSymbolAddress(&p, g_x2);   float* x2   = (float*)p;
    cudaGetSymbolAddress(&p, g_se);   float* se   = (float*)p;
    cudaGetSymbolAddress(&p, g_te);   float* te   = (float*)p;
    cudaGetSymbolAddress(&p, g_sn);   float* sn   = (float*)p;
    cudaGetSymbolAddress(&p, g_tn);   float* tn   = (float*)p;
    cudaGetSymbolAddress(&p, g_v);    float* vv   = (float*)p;
    cudaGetSymbolAddress(&p, g_Mpart);float* Mp   = (float*)p;
    cudaGetSymbolAddress(&p, g_M);    float* M    = (float*)p;
    cudaGetSymbolAddress(&p, g_sim);  float* sim  = (float*)p;
    cudaGetSymbolAddress(&p, g_qi);   float* qi   = (float*)p;
    cudaGetSymbolAddress(&p, g_kvi);  float* kvi  = (float*)p;
    cudaGetSymbolAddress(&p, g_ip);   float* ip   = (float*)p;

    const int SM128 = 2 * (128 + 128) * 36 * 4;   // 73728
    const int SM64  = 2 * (128 +  64) * 36 * 4;   // 55296
    cudaFuncSetAttribute(gemm_tc2<128,0,false>, cudaFuncAttributeMaxDynamicSharedMemorySize, SM128);
    cudaFuncSetAttribute(gemm_tc2<128,1,false>, cudaFuncAttributeMaxDynamicSharedMemorySize, SM128);
    cudaFuncSetAttribute(gemm_tc2<64,0,false>,  cudaFuncAttributeMaxDynamicSharedMemorySize, SM64);
    cudaFuncSetAttribute(gemm_tc2<64,2,false>,  cudaFuncAttributeMaxDynamicSharedMemorySize, SM64);
    cudaFuncSetAttribute(gemm_tc2<64,3,true>,   cudaFuncAttributeMaxDynamicSharedMemorySize, SM64);

    cudaStream_t s0 = cudaStreamPerThread;    // the capturing / main stream
    cudaStream_t s2 = g_s2;

    // fork: bring s2 into the capture graph with a root dependency
    cudaEventRecord(g_e0, s0);
    cudaStreamWaitEvent(s2, g_e0, 0);

    // ---------- branch A (main stream): window attention + FFN ----------
    gemm_tc2<128,0,false><<<dim3(3,128),256,SM128,s0>>>(x, lw_in_w, lw_in_b, qkv, 128, 384, nullptr, nullptr);
    winattn2<<<2048,128,0,s0>>>(qkv, attn);
    gemm_tc2<64,0,false><<<dim3(2,128),256,SM64,s0>>>(attn, lw_out_w, lw_out_b, tmp, 128, 128, nullptr, nullptr);
    ln_kernel<<<NTOK,128,0,s0>>>(tmp, x, ln1_g, ln1_b, x1);
    gemm_tc2<128,1,false><<<dim3(4,128),256,SM128,s0>>>(x1, ffn_w1, ffn_b1, hbuf, 128, 512, nullptr, nullptr);
    gemm_tc2<64,0,false><<<dim3(2,128),256,SM64,s0>>>(hbuf, ffn_w2, ffn_b2, tmp, 512, 128, nullptr, nullptr);
    ln_kernel<<<NTOK,128,0,s0>>>(tmp, x1, ln2_g, ln2_b, x2);

    // ---------- branch B (s2): spatio-temporal similarity + interaction ----------
    gemm_tc2<64,0,false><<<dim3(2,128),256,SM64,s2>>>(spatial,  spat_w, spat_b, se, 128, 128, nullptr, nullptr);
    gemm_tc2<64,0,false><<<dim3(2,128),256,SM64,s2>>>(temporal, temp_w, temp_b, te, 128, 128, nullptr, nullptr);
    normscale2<<<dim3(NTOK/8,2),256,0,s2>>>(se, te, sn, tn);
    macc_tc<<<dim3(16,8),256,0,s2>>>(sn, tn, Mp);
    mreduce<<<(BTCH*128*128)/256,256,0,s2>>>(Mp, M);
    gemm_tc2<64,3,true><<<dim3(2,128),256,SM64,s2>>>(tn, M, nullptr, vv, 128, 128, nullptr, nullptr);
    simdot<<<NTOK/8,256,0,s2>>>(sn, vv, sim);
    gemm_tc2<64,0,false><<<dim3(2,128),256,SM64,s2>>>(se, int_in_w, int_in_b, qi, 128, 128, nullptr, nullptr);
    gemm_tc2<128,0,false><<<dim3(2,128),256,SM128,s2>>>(te, int_in_w + 128*128, int_in_b + 128, kvi, 128, 256, nullptr, nullptr);
    interattn<<<512,256,0,s2>>>(qi, kvi, ip);
    cudaEventRecord(g_e1, s2);

    // ---------- join: out = x2 + sim * (ip @ int_out_w^T + int_out_b) ----------
    cudaStreamWaitEvent(s0, g_e1, 0);
    gemm_tc2<64,2,false><<<dim3(2,128),256,SM64,s0>>>(ip, int_out_w, int_out_b, out, 128, 128, x2, sim);
}

// round 12
// speedup vs baseline: 3.4709x; 1.0486x over previous
#include <cuda_runtime.h>
#include <math.h>
#include <stdint.h>

#define BTCH 8
#define SEQ  2048
#define DIMD 128
#define NTOK (BTCH*SEQ)   /* 16384 */
#define WIN  64
#define NHEAD 8
#define HD   16
#define FFND 512

// ---------------- scratch (device globals; no runtime allocation) ----------------
__device__ float g_qkv [NTOK*384];
__device__ float g_attn[NTOK*DIMD];
__device__ float g_x1  [NTOK*DIMD];
__device__ float g_hbuf[NTOK*FFND];
__device__ float g_x2  [NTOK*DIMD];
__device__ float g_se  [NTOK*DIMD];
__device__ float g_te  [NTOK*DIMD];
__device__ float g_sn  [NTOK*DIMD];
__device__ float g_tn  [NTOK*DIMD];
__device__ float g_Mpart[16*BTCH*DIMD*DIMD];
__device__ float g_M   [BTCH*DIMD*DIMD];
__device__ float g_sim [NTOK];
__device__ float g_qi  [NTOK*DIMD];
__device__ float g_kvi [NTOK*256];
__device__ float g_ip  [NTOK*DIMD];

// ---------------- stream fork resources (created pre-main) ----------------
static cudaStream_t g_s2;
static cudaEvent_t  g_e0, g_e1;
struct StreamInit {
    StreamInit() {
        cudaStreamCreateWithFlags(&g_s2, cudaStreamNonBlocking);
        cudaEventCreateWithFlags(&g_e0, cudaEventDisableTiming);
        cudaEventCreateWithFlags(&g_e1, cudaEventDisableTiming);
    }
};
static StreamInit g_si;

// ---------------- tf32 helpers ----------------
__device__ __forceinline__ uint32_t rtfb(uint32_t raw) {   // fp32 bits -> rna tf32 bits
    uint32_t r;
    asm("cvt.rna.tf32.f32 %0, %1;" : "=r"(r) : "f"(__uint_as_float(raw)));
    return r;
}
__device__ __forceinline__ void mma_tf32(float c[4], const uint32_t a[4], const uint32_t b[2]) {
    asm("mma.sync.aligned.m16n8k8.row.col.f32.tf32.tf32.f32 "
        "{%0,%1,%2,%3}, {%4,%5,%6,%7}, {%8,%9}, {%0,%1,%2,%3};"
        : "+f"(c[0]), "+f"(c[1]), "+f"(c[2]), "+f"(c[3])
        : "r"(a[0]), "r"(a[1]), "r"(a[2]), "r"(a[3]), "r"(b[0]), "r"(b[1]));
}
__device__ __forceinline__ void cpasync16(uint32_t saddr, const float* g) {
    asm volatile("cp.async.cg.shared.global [%0], [%1], 16;\n" :: "r"(saddr), "l"(g));
}

// -------- tensor-core GEMM (tf32, cp.async 2-stage): C = A[M,K] @ W[N,K]^T --------
// BM=128, BK=32, BN=128 (full row per block). 256 threads = 8 warps (2 x 4).
// EPI: 0 bias            1 bias+GELU
//      2 resid + scale[row]*(acc+bias)            (final join)
//      4 LayerNorm(acc + bias + resid)*gam + bet  (fused ln)
//      5 sim[row] = (acc-row . snrow)/SEQ         (no bias; C=sim, resid=sn)
// BATCHW: W advances by 128*128 per 2048 A-rows
template<int EPI, bool BATCHW>
__global__ void gemm_tc2(const float* __restrict__ A, const float* __restrict__ W,
                         const float* __restrict__ bias, float* __restrict__ C,
                         int K, int N,
                         const float* __restrict__ resid, const float* __restrict__ scale,
                         const float* __restrict__ gam, const float* __restrict__ bet)
{
    constexpr int BM = 128, BK = 32, BN = 128;
    constexpr int WM = 64, WN = 32;
    constexpr int MT = 4, NT = 4;
    constexpr int LDS_ = 36;                 // bank = (4*row+col)%32 -> permutation
    constexpr int STG  = (BM + BN) * LDS_;   // words per stage

    extern __shared__ uint32_t sh[];
    const int t = threadIdx.x;
    const int warp = t >> 5, lane = t & 31;
    const int wrow = warp >> 2, wcol = warp & 3;
    const int wm = wrow * WM;
    const int wn = wcol * WN;
    const int g  = lane >> 2;
    const int tq = lane & 3;
    const int m0 = blockIdx.y * BM;
    const int n0 = blockIdx.x * BN;
    const float* Wb = BATCHW ? (W + (size_t)(blockIdx.y >> 4) * 16384) : W;

    const uint32_t sbase = (uint32_t)__cvta_generic_to_shared(sh);
    const int lr = t >> 3;          // 0..31
    const int lc = (t & 7) * 4;     // 0..28

    auto load_stage = [&](int k0, int s) {
        uint32_t off = sbase + (uint32_t)s * STG * 4;
        #pragma unroll
        for (int i = 0; i < 4; i++) {
            int r = lr + 32 * i;
            cpasync16(off + (uint32_t)(r * LDS_ + lc) * 4, A + (size_t)(m0 + r) * K + k0 + lc);
        }
        uint32_t offB = off + (uint32_t)BM * LDS_ * 4;
        #pragma unroll
        for (int i = 0; i < 4; i++) {
            int r = lr + 32 * i;
            cpasync16(offB + (uint32_t)(r * LDS_ + lc) * 4, Wb + (size_t)(n0 + r) * K + k0 + lc);
        }
        asm volatile("cp.async.commit_group;\n" ::);
    };

    float acc[MT][NT][4];
    #pragma unroll
    for (int mi = 0; mi < MT; mi++)
        #pragma unroll
        for (int ni = 0; ni < NT; ni++)
            #pragma unroll
            for (int q = 0; q < 4; q++) acc[mi][ni][q] = 0.f;

    load_stage(0, 0);
    const int KT = K / BK;
    for (int kt = 0; kt < KT; kt++) {
        if (kt + 1 < KT) {
            load_stage((kt + 1) * BK, (kt + 1) & 1);
            asm volatile("cp.async.wait_group 1;\n" ::);
        } else {
            asm volatile("cp.async.wait_group 0;\n" ::);
        }
        __syncthreads();
        const uint32_t (*As)[LDS_] = (const uint32_t(*)[LDS_])(sh + (kt & 1) * STG);
        const uint32_t (*Bs)[LDS_] = (const uint32_t(*)[LDS_])(sh + (kt & 1) * STG + BM * LDS_);
        #pragma unroll
        for (int kk = 0; kk < BK; kk += 8) {
            uint32_t af[MT][4], bf[NT][2];
            #pragma unroll
            for (int mi = 0; mi < MT; mi++) {
                int mr = wm + mi * 16;
                af[mi][0] = rtfb(As[mr + g    ][kk + tq    ]);
                af[mi][1] = rtfb(As[mr + g + 8][kk + tq    ]);
                af[mi][2] = rtfb(As[mr + g    ][kk + tq + 4]);
                af[mi][3] = rtfb(As[mr + g + 8][kk + tq + 4]);
            }
            #pragma unroll
            for (int ni = 0; ni < NT; ni++) {
                int nr = wn + ni * 8;
                bf[ni][0] = rtfb(Bs[nr + g][kk + tq    ]);
                bf[ni][1] = rtfb(Bs[nr + g][kk + tq + 4]);
            }
            #pragma unroll
            for (int mi = 0; mi < MT; mi++)
                #pragma unroll
                for (int ni = 0; ni < NT; ni++)
                    mma_tf32(acc[mi][ni], af[mi], bf[ni]);
        }
        __syncthreads();
    }
    // (mainloop ends with __syncthreads -> smem reusable below)

    if (EPI == 4) {
        // ---- fused residual + LayerNorm over the full 128-col row ----
        float ps[8], pq[8];
        #pragma unroll
        for (int i = 0; i < 8; i++) { ps[i] = 0.f; pq[i] = 0.f; }
        #pragma unroll
        for (int mi = 0; mi < MT; mi++) {
            #pragma unroll
            for (int ni = 0; ni < NT; ni++) {
                int nn = wn + ni * 8 + tq * 2;
                float b0 = bias[nn], b1 = bias[nn + 1];
                #pragma unroll
                for (int half = 0; half < 2; half++) {
                    int lm = wm + mi * 16 + g + half * 8;
                    size_t gm = (size_t)(m0 + lm);
                    float v0 = acc[mi][ni][half*2+0] + b0 + resid[gm*128 + nn];
                    float v1 = acc[mi][ni][half*2+1] + b1 + resid[gm*128 + nn + 1];
                    acc[mi][ni][half*2+0] = v0;
                    acc[mi][ni][half*2+1] = v1;
                    int ri = mi*2 + half;
                    ps[ri] += v0 + v1;
                    pq[ri] += v0*v0 + v1*v1;
                }
            }
        }
        #pragma unroll
        for (int off = 1; off <= 2; off <<= 1)
            #pragma unroll
            for (int i = 0; i < 8; i++) {
                ps[i] += __shfl_xor_sync(0xffffffff, ps[i], off);
                pq[i] += __shfl_xor_sync(0xffffffff, pq[i], off);
            }
        float* rs = (float*)sh;        // [128][4]
        float* rq = rs + 512;
        if (tq == 0) {
            #pragma unroll
            for (int i = 0; i < 8; i++) {
                int lm = wm + (i >> 1) * 16 + g + (i & 1) * 8;
                rs[lm*4 + wcol] = ps[i];
                rq[lm*4 + wcol] = pq[i];
            }
        }
        __syncthreads();
        #pragma unroll
        for (int mi = 0; mi < MT; mi++) {
            #pragma unroll
            for (int half = 0; half < 2; half++) {
                int lm = wm + mi * 16 + g + half * 8;
                float su = rs[lm*4+0] + rs[lm*4+1] + rs[lm*4+2] + rs[lm*4+3];
                float sq = rq[lm*4+0] + rq[lm*4+1] + rq[lm*4+2] + rq[lm*4+3];
                float mu = su * (1.f/128.f);
                float var = sq * (1.f/128.f) - mu*mu;
                float rstd = rsqrtf(var + 1e-5f);
                size_t gm = (size_t)(m0 + lm);
                #pragma unroll
                for (int ni = 0; ni < NT; ni++) {
                    int nn = wn + ni * 8 + tq * 2;
                    float o0 = (acc[mi][ni][half*2+0] - mu) * rstd * gam[nn]   + bet[nn];
                    float o1 = (acc[mi][ni][half*2+1] - mu) * rstd * gam[nn+1] + bet[nn+1];
                    *(float2*)&C[gm*128 + nn] = make_float2(o0, o1);
                }
            }
        }
        return;
    }

    if (EPI == 5) {
        // ---- sim[row] = (acc_row . sn_row) / SEQ ; resid == sn, C == sim ----
        float ps[8];
        #pragma unroll
        for (int i = 0; i < 8; i++) ps[i] = 0.f;
        #pragma unroll
        for (int mi = 0; mi < MT; mi++) {
            #pragma unroll
            for (int ni = 0; ni < NT; ni++) {
                int nn = wn + ni * 8 + tq * 2;
                #pragma unroll
                for (int half = 0; half < 2; half++) {
                    int lm = wm + mi * 16 + g + half * 8;
                    size_t gm = (size_t)(m0 + lm);
                    ps[mi*2+half] += acc[mi][ni][half*2+0] * resid[gm*128 + nn]
                                   + acc[mi][ni][half*2+1] * resid[gm*128 + nn + 1];
                }
            }
        }
        #pragma unroll
        for (int off = 1; off <= 2; off <<= 1)
            #pragma unroll
            for (int i = 0; i < 8; i++)
                ps[i] += __shfl_xor_sync(0xffffffff, ps[i], off);
        float* rs = (float*)sh;        // [128][4]
        if (tq == 0) {
            #pragma unroll
            for (int i = 0; i < 8; i++) {
                int lm = wm + (i >> 1) * 16 + g + (i & 1) * 8;
                rs[lm*4 + wcol] = ps[i];
            }
        }
        __syncthreads();
        if (wcol == 0 && tq == 0) {
            #pragma unroll
            for (int i = 0; i < 8; i++) {
                int lm = wm + (i >> 1) * 16 + g + (i & 1) * 8;
                float su = rs[lm*4+0] + rs[lm*4+1] + rs[lm*4+2] + rs[lm*4+3];
                C[m0 + lm] = su * (1.f / (float)SEQ);
            }
        }
        return;
    }

    #pragma unroll
    for (int mi = 0; mi < MT; mi++) {
        #pragma unroll
        for (int ni = 0; ni < NT; ni++) {
            int m = m0 + wm + mi * 16 + g;
            int nn = n0 + wn + ni * 8 + tq * 2;
            float b0 = bias[nn], b1 = bias[nn + 1];
            #pragma unroll
            for (int half = 0; half < 2; half++) {
                int mm = m + half * 8;
                float v0 = acc[mi][ni][half*2 + 0] + b0;
                float v1 = acc[mi][ni][half*2 + 1] + b1;
                if (EPI == 1) {
                    v0 = 0.5f * v0 * (1.f + erff(v0 * 0.70710678118654752f));
                    v1 = 0.5f * v1 * (1.f + erff(v1 * 0.70710678118654752f));
                }
                if (EPI == 2) {
                    float sc = scale[mm];
                    v0 = resid[(size_t)mm * N + nn    ] + sc * v0;
                    v1 = resid[(size_t)mm * N + nn + 1] + sc * v1;
                }
                *(float2*)&C[(size_t)mm * N + nn] = make_float2(v0, v1);
            }
        }
    }
}

// ------- local-window causal attention: one block per (window, head) -------
__global__ void winattn2(const float* __restrict__ qkv, float* __restrict__ out)
{
    __shared__ float qs[WIN][17], ks[WIN][17], vs[WIN][17], sc[WIN][65];
    const int w = blockIdx.x >> 3, h = blockIdx.x & 7;
    const int base = w * WIN;
    const int t = threadIdx.x;   // 128
    #pragma unroll
    for (int i = 0; i < 8; i++) {
        int idx = t + 128*i; int r = idx >> 4, c = idx & 15;
        size_t rb = (size_t)(base + r) * 384 + h*16 + c;
        qs[r][c] = qkv[rb];
        ks[r][c] = qkv[rb + 128];
        vs[r][c] = qkv[rb + 256];
    }
    __syncthreads();
    #pragma unroll
    for (int i = 0; i < 32; i++) {
        int idx = t + 128*i; int row = idx >> 6, j = idx & 63;
        float s = 0.f;
        #pragma unroll
        for (int d = 0; d < 16; d++) s += qs[row][d] * ks[j][d];
        sc[row][j] = s * 0.25f;
    }
    __syncthreads();
    if (t < 64) {
        int i = t;
        float mx = -1e30f;
        for (int j = 0; j <= i; j++) mx = fmaxf(mx, sc[i][j]);
        float sum = 0.f;
        for (int j = 0; j <= i; j++) { float p = expf(sc[i][j] - mx); sc[i][j] = p; sum += p; }
        float inv = 1.f / sum;
        for (int j = 0; j <= i; j++) sc[i][j] *= inv;
        for (int j = i + 1; j < 64; j++) sc[i][j] = 0.f;
    }
    __syncthreads();
    #pragma unroll
    for (int i2 = 0; i2 < 8; i2++) {
        int idx = t + 128*i2; int i = idx >> 4, d = idx & 15;
        float s = 0.f;
        for (int j = 0; j < 64; j++) s += sc[i][j] * vs[j][d];
        out[(size_t)(base + i) * 128 + h*16 + d] = s;
    }
}

// ------- cos-normalize both se->sn and te->tn (grid.y selects) -------
__global__ void normscale2(const float* __restrict__ se, const float* __restrict__ te,
                           float* __restrict__ sn, float* __restrict__ tn)
{
    const float* x   = blockIdx.y ? te : se;
    float*       out = blockIdx.y ? tn : sn;
    int row = blockIdx.x * 8 + (threadIdx.x >> 5);
    int lane = threadIdx.x & 31;
    const float* p = x + (size_t)row * 128;
    float v[4];
    float s = 0.f;
    #pragma unroll
    for (int c = 0; c < 4; c++) { v[c] = p[lane + c*32]; s += v[c] * v[c]; }
    #pragma unroll
    for (int o = 16; o > 0; o >>= 1) s += __shfl_xor_sync(0xffffffff, s, o);
    float inv = 1.f / fmaxf(sqrtf(s), 1e-8f);
    float* q = out + (size_t)row * 128;
    #pragma unroll
    for (int c = 0; c < 4; c++) q[lane + c*32] = v[c] * inv;
}

// ------- M partials via tensor cores: Mpart[p,b] = sn_chunk^T @ tn_chunk -------
__global__ void macc_tc(const float* __restrict__ sn, const float* __restrict__ tn,
                        float* __restrict__ Mpart)
{
    constexpr int LDSm = 136;
    __shared__ uint32_t sns[32][LDSm], tns[32][LDSm];
    const int t = threadIdx.x;
    const int warp = t >> 5, lane = t & 31;
    const int wm = (warp >> 2) * 64, wn = (warp & 3) * 32;
    const int g = lane >> 2, tq = lane & 3;
    const size_t row0 = (size_t)blockIdx.y * SEQ + blockIdx.x * 128;

    float acc[4][4][4];
    #pragma unroll
    for (int mi = 0; mi < 4; mi++)
        #pragma unroll
        for (int ni = 0; ni < 4; ni++)
            #pragma unroll
            for (int q = 0; q < 4; q++) acc[mi][ni][q] = 0.f;

    for (int c0 = 0; c0 < 128; c0 += 32) {
        #pragma unroll
        for (int i = 0; i < 4; i++) {
            int idx = t + 256*i; int r = idx >> 5; int c4 = (idx & 31) * 4;
            float4 a = *(const float4*)&sn[(row0 + c0 + r) * 128 + c4];
            float4 b = *(const float4*)&tn[(row0 + c0 + r) * 128 + c4];
            *(float4*)&sns[r][c4] = a;
            *(float4*)&tns[r][c4] = b;
        }
        __syncthreads();
        #pragma unroll
        for (int kk = 0; kk < 32; kk += 8) {
            uint32_t af[4][4], bf[4][2];
            #pragma unroll
            for (int mi = 0; mi < 4; mi++) {
                int m = wm + mi * 16;
                af[mi][0] = rtfb(sns[kk + tq    ][m + g    ]);
                af[mi][1] = rtfb(sns[kk + tq    ][m + g + 8]);
                af[mi][2] = rtfb(sns[kk + tq + 4][m + g    ]);
                af[mi][3] = rtfb(sns[kk + tq + 4][m + g + 8]);
            }
            #pragma unroll
            for (int ni = 0; ni < 4; ni++) {
                int n = wn + ni * 8 + g;
                bf[ni][0] = rtfb(tns[kk + tq    ][n]);
                bf[ni][1] = rtfb(tns[kk + tq + 4][n]);
            }
            #pragma unroll
            for (int mi = 0; mi < 4; mi++)
                #pragma unroll
                for (int ni = 0; ni < 4; ni++)
                    mma_tf32(acc[mi][ni], af[mi], bf[ni]);
        }
        __syncthreads();
    }
    float* o = Mpart + ((size_t)blockIdx.x * BTCH + blockIdx.y) * 16384;
    #pragma unroll
    for (int mi = 0; mi < 4; mi++) {
        #pragma unroll
        for (int ni = 0; ni < 4; ni++) {
            int m = wm + mi * 16 + g;
            int nn = wn + ni * 8 + tq * 2;
            o[m*128 + nn]       = acc[mi][ni][0];
            o[m*128 + nn + 1]   = acc[mi][ni][1];
            o[(m+8)*128 + nn]   = acc[mi][ni][2];
            o[(m+8)*128 + nn+1] = acc[mi][ni][3];
        }
    }
}

__global__ void mreduce(const float* __restrict__ Mpart, float* __restrict__ M)
{
    int idx = blockIdx.x * 256 + threadIdx.x;   // 8*16384 total
    float s = 0.f;
    #pragma unroll
    for (int p = 0; p < 16; p++) s += Mpart[(size_t)p * (BTCH*128*128) + idx];
    M[idx] = s;
}

// ------- interaction attention: len=8 (batch axis), batch=S, 8 heads of 16 -------
__global__ void interattn(const float* __restrict__ qb, const float* __restrict__ kvb,
                          float* __restrict__ out)
{
    int gid = blockIdx.x * 256 + threadIdx.x;     // 2048*8*8 = 131072 threads
    int s = gid >> 6; int r = gid & 63; int h = r >> 3; int i = r & 7;
    const float* q = qb + ((size_t)i * SEQ + s) * 128 + h*16;
    float qr[16];
    #pragma unroll
    for (int d = 0; d < 16; d++) qr[d] = q[d];
    float sc[8];
    float mx = -1e30f;
    #pragma unroll
    for (int j = 0; j < 8; j++) {
        const float* k = kvb + ((size_t)j * SEQ + s) * 256 + h*16;
        float a = 0.f;
        #pragma unroll
        for (int d = 0; d < 16; d++) a += qr[d] * k[d];
        sc[j] = a * 0.25f;
        mx = fmaxf(mx, sc[j]);
    }
    float sum = 0.f;
    #pragma unroll
    for (int j = 0; j < 8; j++) { sc[j] = expf(sc[j] - mx); sum += sc[j]; }
    float inv = 1.f / sum;
    float o[16];
    #pragma unroll
    for (int d = 0; d < 16; d++) o[d] = 0.f;
    #pragma unroll
    for (int j = 0; j < 8; j++) {
        const float* v = kvb + ((size_t)j * SEQ + s) * 256 + 128 + h*16;
        float p = sc[j] * inv;
        #pragma unroll
        for (int d = 0; d < 16; d++) o[d] += p * v[d];
    }
    float* op = out + ((size_t)i * SEQ + s) * 128 + h*16;
    #pragma unroll
    for (int d = 0; d < 16; d++) op[d] = o[d];
}

// ==================================================================================
extern "C" void kernel_launch(void* const* d_in, const int* in_sizes, int n_in,
                              void* d_out, int out_size)
{
    const float* x        = (const float*)d_in[0];
    const float* spatial  = (const float*)d_in[1];
    const float* temporal = (const float*)d_in[2];
    const float* lw_in_w  = (const float*)d_in[3];
    const float* lw_in_b  = (const float*)d_in[4];
    const float* lw_out_w = (const float*)d_in[5];
    const float* lw_out_b = (const float*)d_in[6];
    const float* spat_w   = (const float*)d_in[7];
    const float* spat_b   = (const float*)d_in[8];
    const float* temp_w   = (const float*)d_in[9];
    const float* temp_b   = (const float*)d_in[10];
    const float* int_in_w = (const float*)d_in[11];
    const float* int_in_b = (const float*)d_in[12];
    const float* int_out_w= (const float*)d_in[13];
    const float* int_out_b= (const float*)d_in[14];
    const float* ffn_w1   = (const float*)d_in[15];
    const float* ffn_b1   = (const float*)d_in[16];
    const float* ffn_w2   = (const float*)d_in[17];
    const float* ffn_b2   = (const float*)d_in[18];
    const float* ln1_g    = (const float*)d_in[19];
    const float* ln1_b    = (const float*)d_in[20];
    const float* ln2_g    = (const float*)d_in[21];
    const float* ln2_b    = (const float*)d_in[22];
    float* out = (float*)d_out;

    void *p;
    cudaGetSymbolAddress(&p, g_qkv);  float* qkv  = (float*)p;
    cudaGetSymbolAddress(&p, g_attn); float* attn = (float*)p;
    cudaGetSymbolAddress(&p, g_x1);   float* x1   = (float*)p;
    cudaGetSymbolAddress(&p, g_hbuf); float* hbuf = (float*)p;
    cudaGetSymbolAddress(&p, g_x2);   float* x2   = (float*)p;
    cudaGetSymbolAddress(&p, g_se);   float* se   = (float*)p;
    cudaGetSymbolAddress(&p, g_te);   float* te   = (float*)p;
    cudaGetSymbolAddress(&p, g_sn);   float* sn   = (float*)p;
    cudaGetSymbolAddress(&p, g_tn);   float* tn   = (float*)p;
    cudaGetSymbolAddress(&p, g_Mpart);float* Mp   = (float*)p;
    cudaGetSymbolAddress(&p, g_M);    float* M    = (float*)p;
    cudaGetSymbolAddress(&p, g_sim);  float* sim  = (float*)p;
    cudaGetSymbolAddress(&p, g_qi);   float* qi   = (float*)p;
    cudaGetSymbolAddress(&p, g_kvi);  float* kvi  = (float*)p;
    cudaGetSymbolAddress(&p, g_ip);   float* ip   = (float*)p;

    const int SMEM = 2 * (128 + 128) * 36 * 4;   // 73728 (>= 4KB epilogue scratch)
    cudaFuncSetAttribute(gemm_tc2<0,false>, cudaFuncAttributeMaxDynamicSharedMemorySize, SMEM);
    cudaFuncSetAttribute(gemm_tc2<1,false>, cudaFuncAttributeMaxDynamicSharedMemorySize, SMEM);
    cudaFuncSetAttribute(gemm_tc2<2,false>, cudaFuncAttributeMaxDynamicSharedMemorySize, SMEM);
    cudaFuncSetAttribute(gemm_tc2<4,false>, cudaFuncAttributeMaxDynamicSharedMemorySize, SMEM);
    cudaFuncSetAttribute(gemm_tc2<5,true>,  cudaFuncAttributeMaxDynamicSharedMemorySize, SMEM);

    cudaStream_t s0 = cudaStreamPerThread;    // the capturing / main stream
    cudaStream_t s2 = g_s2;

    // fork: bring s2 into the capture graph with a root dependency
    cudaEventRecord(g_e0, s0);
    cudaStreamWaitEvent(s2, g_e0, 0);

    // ---------- branch A (main stream): window attention + FFN ----------
    gemm_tc2<0,false><<<dim3(3,128),256,SMEM,s0>>>(x, lw_in_w, lw_in_b, qkv, 128, 384, nullptr, nullptr, nullptr, nullptr);
    winattn2<<<2048,128,0,s0>>>(qkv, attn);
    gemm_tc2<4,false><<<dim3(1,128),256,SMEM,s0>>>(attn, lw_out_w, lw_out_b, x1, 128, 128, x, nullptr, ln1_g, ln1_b);
    gemm_tc2<1,false><<<dim3(4,128),256,SMEM,s0>>>(x1, ffn_w1, ffn_b1, hbuf, 128, 512, nullptr, nullptr, nullptr, nullptr);
    gemm_tc2<4,false><<<dim3(1,128),256,SMEM,s0>>>(hbuf, ffn_w2, ffn_b2, x2, 512, 128, x1, nullptr, ln2_g, ln2_b);

    // ---------- branch B (s2): spatio-temporal similarity + interaction ----------
    gemm_tc2<0,false><<<dim3(1,128),256,SMEM,s2>>>(spatial,  spat_w, spat_b, se, 128, 128, nullptr, nullptr, nullptr, nullptr);
    gemm_tc2<0,false><<<dim3(1,128),256,SMEM,s2>>>(temporal, temp_w, temp_b, te, 128, 128, nullptr, nullptr, nullptr, nullptr);
    normscale2<<<dim3(NTOK/8,2),256,0,s2>>>(se, te, sn, tn);
    macc_tc<<<dim3(16,8),256,0,s2>>>(sn, tn, Mp);
    mreduce<<<(BTCH*128*128)/256,256,0,s2>>>(Mp, M);
    // sim = (sn . (M @ tn)) / SEQ, fused in-epilogue
    gemm_tc2<5,true><<<dim3(1,128),256,SMEM,s2>>>(tn, M, nullptr, sim, 128, 128, sn, nullptr, nullptr, nullptr);
    gemm_tc2<0,false><<<dim3(1,128),256,SMEM,s2>>>(se, int_in_w, int_in_b, qi, 128, 128, nullptr, nullptr, nullptr, nullptr);
    gemm_tc2<0,false><<<dim3(2,128),256,SMEM,s2>>>(te, int_in_w + 128*128, int_in_b + 128, kvi, 128, 256, nullptr, nullptr, nullptr, nullptr);
    interattn<<<512,256,0,s2>>>(qi, kvi, ip);
    cudaEventRecord(g_e1, s2);

    // ---------- join: out = x2 + sim * (ip @ int_out_w^T + int_out_b) ----------
    cudaStreamWaitEvent(s0, g_e1, 0);
    gemm_tc2<2,false><<<dim3(1,128),256,SMEM,s0>>>(ip, int_out_w, int_out_b, out, 128, 128, x2, sim, nullptr, nullptr);
}

// round 13
// speedup vs baseline: 3.7151x; 1.0704x over previous
#include <cuda_runtime.h>
#include <math.h>
#include <stdint.h>

#define BTCH 8
#define SEQ  2048
#define DIMD 128
#define NTOK (BTCH*SEQ)   /* 16384 */
#define WIN  64
#define NHEAD 8
#define HD   16
#define FFND 512

// ---------------- scratch (device globals; no runtime allocation) ----------------
__device__ float g_qkv [NTOK*384];
__device__ float g_attn[NTOK*DIMD];
__device__ float g_x1  [NTOK*DIMD];
__device__ float g_hbuf[NTOK*FFND];
__device__ float g_x2  [NTOK*DIMD];
__device__ float g_se  [NTOK*DIMD];
__device__ float g_te  [NTOK*DIMD];
__device__ float g_sn  [NTOK*DIMD];
__device__ float g_tn  [NTOK*DIMD];
__device__ float g_Mpart[16*BTCH*DIMD*DIMD];
__device__ float g_M   [BTCH*DIMD*DIMD];
__device__ float g_sim [NTOK];
__device__ float g_qi  [NTOK*DIMD];
__device__ float g_kvi [NTOK*256];
__device__ float g_ip  [NTOK*DIMD];

// ---------------- stream fork resources (created pre-main) ----------------
static cudaStream_t g_s2;
static cudaEvent_t  g_e0, g_e1;
struct StreamInit {
    StreamInit() {
        cudaStreamCreateWithFlags(&g_s2, cudaStreamNonBlocking);
        cudaEventCreateWithFlags(&g_e0, cudaEventDisableTiming);
        cudaEventCreateWithFlags(&g_e1, cudaEventDisableTiming);
    }
};
static StreamInit g_si;

// ---------------- tf32 helpers ----------------
__device__ __forceinline__ uint32_t rtfb(uint32_t raw) {   // fp32 bits -> rna tf32 bits
    uint32_t r;
    asm("cvt.rna.tf32.f32 %0, %1;" : "=r"(r) : "f"(__uint_as_float(raw)));
    return r;
}
__device__ __forceinline__ void mma_tf32(float c[4], const uint32_t a[4], const uint32_t b[2]) {
    asm("mma.sync.aligned.m16n8k8.row.col.f32.tf32.tf32.f32 "
        "{%0,%1,%2,%3}, {%4,%5,%6,%7}, {%8,%9}, {%0,%1,%2,%3};"
        : "+f"(c[0]), "+f"(c[1]), "+f"(c[2]), "+f"(c[3])
        : "r"(a[0]), "r"(a[1]), "r"(a[2]), "r"(a[3]), "r"(b[0]), "r"(b[1]));
}
__device__ __forceinline__ void cpasync16(uint32_t saddr, const float* g) {
    asm volatile("cp.async.cg.shared.global [%0], [%1], 16;\n" :: "r"(saddr), "l"(g));
}

// -------- tensor-core GEMM (tf32, cp.async 2-stage): C = A[M,K] @ W[N,K]^T --------
// BM=128, BK=32, BN=128 (full row per block). 256 threads = 8 warps (2 x 4).
// __launch_bounds__(256,2): cap regs at 128 so 2 CTAs co-reside per SM (occ 25%).
// EPI: 0 bias            1 bias+GELU
//      2 resid + scale[row]*(acc+bias)            (final join)
//      4 LayerNorm(acc + bias + resid)*gam + bet  (fused ln)
//      5 sim[row] = (acc-row . snrow)/SEQ         (no bias; C=sim, resid=sn)
//      6 dual bias GEMM: blockIdx.z==1 uses (resid,scale,gam,bet) as (A2,W2,b2,C2)
// BATCHW: W advances by 128*128 per 2048 A-rows
template<int EPI, bool BATCHW>
__global__ void __launch_bounds__(256, 2)
gemm_tc2(const float* __restrict__ A, const float* __restrict__ W,
         const float* __restrict__ bias, float* __restrict__ C,
         int K, int N,
         const float* __restrict__ resid, const float* __restrict__ scale,
         const float* __restrict__ gam, const float* __restrict__ bet)
{
    constexpr int BM = 128, BK = 32, BN = 128;
    constexpr int WM = 64, WN = 32;
    constexpr int MT = 4, NT = 4;
    constexpr int LDS_ = 36;                 // bank = (4*row+col)%32 -> permutation
    constexpr int STG  = (BM + BN) * LDS_;   // words per stage

    // dual-job pointer selection (EPI==6)
    const float* A_   = A;
    const float* W_   = W;
    const float* bias_= bias;
    float*       C_   = C;
    if (EPI == 6 && blockIdx.z == 1) {
        A_ = resid; W_ = scale; bias_ = gam; C_ = (float*)bet;
    }

    extern __shared__ uint32_t sh[];
    const int t = threadIdx.x;
    const int warp = t >> 5, lane = t & 31;
    const int wrow = warp >> 2, wcol = warp & 3;
    const int wm = wrow * WM;
    const int wn = wcol * WN;
    const int g  = lane >> 2;
    const int tq = lane & 3;
    const int m0 = blockIdx.y * BM;
    const int n0 = blockIdx.x * BN;
    const float* Wb = BATCHW ? (W_ + (size_t)(blockIdx.y >> 4) * 16384) : W_;

    const uint32_t sbase = (uint32_t)__cvta_generic_to_shared(sh);
    const int lr = t >> 3;          // 0..31
    const int lc = (t & 7) * 4;     // 0..28

    auto load_stage = [&](int k0, int s) {
        uint32_t off = sbase + (uint32_t)s * STG * 4;
        #pragma unroll
        for (int i = 0; i < 4; i++) {
            int r = lr + 32 * i;
            cpasync16(off + (uint32_t)(r * LDS_ + lc) * 4, A_ + (size_t)(m0 + r) * K + k0 + lc);
        }
        uint32_t offB = off + (uint32_t)BM * LDS_ * 4;
        #pragma unroll
        for (int i = 0; i < 4; i++) {
            int r = lr + 32 * i;
            cpasync16(offB + (uint32_t)(r * LDS_ + lc) * 4, Wb + (size_t)(n0 + r) * K + k0 + lc);
        }
        asm volatile("cp.async.commit_group;\n" ::);
    };

    float acc[MT][NT][4];
    #pragma unroll
    for (int mi = 0; mi < MT; mi++)
        #pragma unroll
        for (int ni = 0; ni < NT; ni++)
            #pragma unroll
            for (int q = 0; q < 4; q++) acc[mi][ni][q] = 0.f;

    load_stage(0, 0);
    const int KT = K / BK;
    for (int kt = 0; kt < KT; kt++) {
        if (kt + 1 < KT) {
            load_stage((kt + 1) * BK, (kt + 1) & 1);
            asm volatile("cp.async.wait_group 1;\n" ::);
        } else {
            asm volatile("cp.async.wait_group 0;\n" ::);
        }
        __syncthreads();
        const uint32_t (*As)[LDS_] = (const uint32_t(*)[LDS_])(sh + (kt & 1) * STG);
        const uint32_t (*Bs)[LDS_] = (const uint32_t(*)[LDS_])(sh + (kt & 1) * STG + BM * LDS_);
        #pragma unroll
        for (int kk = 0; kk < BK; kk += 8) {
            uint32_t af[MT][4], bf[NT][2];
            #pragma unroll
            for (int mi = 0; mi < MT; mi++) {
                int mr = wm + mi * 16;
                af[mi][0] = rtfb(As[mr + g    ][kk + tq    ]);
                af[mi][1] = rtfb(As[mr + g + 8][kk + tq    ]);
                af[mi][2] = rtfb(As[mr + g    ][kk + tq + 4]);
                af[mi][3] = rtfb(As[mr + g + 8][kk + tq + 4]);
            }
            #pragma unroll
            for (int ni = 0; ni < NT; ni++) {
                int nr = wn + ni * 8;
                bf[ni][0] = rtfb(Bs[nr + g][kk + tq    ]);
                bf[ni][1] = rtfb(Bs[nr + g][kk + tq + 4]);
            }
            #pragma unroll
            for (int mi = 0; mi < MT; mi++)
                #pragma unroll
                for (int ni = 0; ni < NT; ni++)
                    mma_tf32(acc[mi][ni], af[mi], bf[ni]);
        }
        __syncthreads();
    }
    // (mainloop ends with __syncthreads -> smem reusable below)

    if (EPI == 4) {
        // ---- fused residual + LayerNorm over the full 128-col row ----
        float ps[8], pq[8];
        #pragma unroll
        for (int i = 0; i < 8; i++) { ps[i] = 0.f; pq[i] = 0.f; }
        #pragma unroll
        for (int mi = 0; mi < MT; mi++) {
            #pragma unroll
            for (int ni = 0; ni < NT; ni++) {
                int nn = wn + ni * 8 + tq * 2;
                float b0 = bias_[nn], b1 = bias_[nn + 1];
                #pragma unroll
                for (int half = 0; half < 2; half++) {
                    int lm = wm + mi * 16 + g + half * 8;
                    size_t gm = (size_t)(m0 + lm);
                    float v0 = acc[mi][ni][half*2+0] + b0 + resid[gm*128 + nn];
                    float v1 = acc[mi][ni][half*2+1] + b1 + resid[gm*128 + nn + 1];
                    acc[mi][ni][half*2+0] = v0;
                    acc[mi][ni][half*2+1] = v1;
                    int ri = mi*2 + half;
                    ps[ri] += v0 + v1;
                    pq[ri] += v0*v0 + v1*v1;
                }
            }
        }
        #pragma unroll
        for (int off = 1; off <= 2; off <<= 1)
            #pragma unroll
            for (int i = 0; i < 8; i++) {
                ps[i] += __shfl_xor_sync(0xffffffff, ps[i], off);
                pq[i] += __shfl_xor_sync(0xffffffff, pq[i], off);
            }
        float* rs = (float*)sh;        // [128][4]
        float* rq = rs + 512;
        if (tq == 0) {
            #pragma unroll
            for (int i = 0; i < 8; i++) {
                int lm = wm + (i >> 1) * 16 + g + (i & 1) * 8;
                rs[lm*4 + wcol] = ps[i];
                rq[lm*4 + wcol] = pq[i];
            }
        }
        __syncthreads();
        #pragma unroll
        for (int mi = 0; mi < MT; mi++) {
            #pragma unroll
            for (int half = 0; half < 2; half++) {
                int lm = wm + mi * 16 + g + half * 8;
                float su = rs[lm*4+0] + rs[lm*4+1] + rs[lm*4+2] + rs[lm*4+3];
                float sq = rq[lm*4+0] + rq[lm*4+1] + rq[lm*4+2] + rq[lm*4+3];
                float mu = su * (1.f/128.f);
                float var = sq * (1.f/128.f) - mu*mu;
                float rstd = rsqrtf(var + 1e-5f);
                size_t gm = (size_t)(m0 + lm);
                #pragma unroll
                for (int ni = 0; ni < NT; ni++) {
                    int nn = wn + ni * 8 + tq * 2;
                    float o0 = (acc[mi][ni][half*2+0] - mu) * rstd * gam[nn]   + bet[nn];
                    float o1 = (acc[mi][ni][half*2+1] - mu) * rstd * gam[nn+1] + bet[nn+1];
                    *(float2*)&C_[gm*128 + nn] = make_float2(o0, o1);
                }
            }
        }
        return;
    }

    if (EPI == 5) {
        // ---- sim[row] = (acc_row . sn_row) / SEQ ; resid == sn, C == sim ----
        float ps[8];
        #pragma unroll
        for (int i = 0; i < 8; i++) ps[i] = 0.f;
        #pragma unroll
        for (int mi = 0; mi < MT; mi++) {
            #pragma unroll
            for (int ni = 0; ni < NT; ni++) {
                int nn = wn + ni * 8 + tq * 2;
                #pragma unroll
                for (int half = 0; half < 2; half++) {
                    int lm = wm + mi * 16 + g + half * 8;
                    size_t gm = (size_t)(m0 + lm);
                    ps[mi*2+half] += acc[mi][ni][half*2+0] * resid[gm*128 + nn]
                                   + acc[mi][ni][half*2+1] * resid[gm*128 + nn + 1];
                }
            }
        }
        #pragma unroll
        for (int off = 1; off <= 2; off <<= 1)
            #pragma unroll
            for (int i = 0; i < 8; i++)
                ps[i] += __shfl_xor_sync(0xffffffff, ps[i], off);
        float* rs = (float*)sh;        // [128][4]
        if (tq == 0) {
            #pragma unroll
            for (int i = 0; i < 8; i++) {
                int lm = wm + (i >> 1) * 16 + g + (i & 1) * 8;
                rs[lm*4 + wcol] = ps[i];
            }
        }
        __syncthreads();
        if (wcol == 0 && tq == 0) {
            #pragma unroll
            for (int i = 0; i < 8; i++) {
                int lm = wm + (i >> 1) * 16 + g + (i & 1) * 8;
                float su = rs[lm*4+0] + rs[lm*4+1] + rs[lm*4+2] + rs[lm*4+3];
                C_[m0 + lm] = su * (1.f / (float)SEQ);
            }
        }
        return;
    }

    #pragma unroll
    for (int mi = 0; mi < MT; mi++) {
        #pragma unroll
        for (int ni = 0; ni < NT; ni++) {
            int m = m0 + wm + mi * 16 + g;
            int nn = n0 + wn + ni * 8 + tq * 2;
            float b0 = bias_[nn], b1 = bias_[nn + 1];
            #pragma unroll
            for (int half = 0; half < 2; half++) {
                int mm = m + half * 8;
                float v0 = acc[mi][ni][half*2 + 0] + b0;
                float v1 = acc[mi][ni][half*2 + 1] + b1;
                if (EPI == 1) {
                    v0 = 0.5f * v0 * (1.f + erff(v0 * 0.70710678118654752f));
                    v1 = 0.5f * v1 * (1.f + erff(v1 * 0.70710678118654752f));
                }
                if (EPI == 2) {
                    float sc = scale[mm];
                    v0 = resid[(size_t)mm * N + nn    ] + sc * v0;
                    v1 = resid[(size_t)mm * N + nn + 1] + sc * v1;
                }
                *(float2*)&C_[(size_t)mm * N + nn] = make_float2(v0, v1);
            }
        }
    }
}

// ------- local-window causal attention: one block per (window, head) -------
__global__ void winattn2(const float* __restrict__ qkv, float* __restrict__ out)
{
    __shared__ float qs[WIN][17], ks[WIN][17], vs[WIN][17], sc[WIN][65];
    const int w = blockIdx.x >> 3, h = blockIdx.x & 7;
    const int base = w * WIN;
    const int t = threadIdx.x;   // 128
    #pragma unroll
    for (int i = 0; i < 8; i++) {
        int idx = t + 128*i; int r = idx >> 4, c = idx & 15;
        size_t rb = (size_t)(base + r) * 384 + h*16 + c;
        qs[r][c] = qkv[rb];
        ks[r][c] = qkv[rb + 128];
        vs[r][c] = qkv[rb + 256];
    }
    __syncthreads();
    #pragma unroll
    for (int i = 0; i < 32; i++) {
        int idx = t + 128*i; int row = idx >> 6, j = idx & 63;
        float s = 0.f;
        #pragma unroll
        for (int d = 0; d < 16; d++) s += qs[row][d] * ks[j][d];
        sc[row][j] = s * 0.25f;
    }
    __syncthreads();
    if (t < 64) {
        int i = t;
        float mx = -1e30f;
        for (int j = 0; j <= i; j++) mx = fmaxf(mx, sc[i][j]);
        float sum = 0.f;
        for (int j = 0; j <= i; j++) { float p = expf(sc[i][j] - mx); sc[i][j] = p; sum += p; }
        float inv = 1.f / sum;
        for (int j = 0; j <= i; j++) sc[i][j] *= inv;
        for (int j = i + 1; j < 64; j++) sc[i][j] = 0.f;
    }
    __syncthreads();
    #pragma unroll
    for (int i2 = 0; i2 < 8; i2++) {
        int idx = t + 128*i2; int i = idx >> 4, d = idx & 15;
        float s = 0.f;
        for (int j = 0; j < 64; j++) s += sc[i][j] * vs[j][d];
        out[(size_t)(base + i) * 128 + h*16 + d] = s;
    }
}

// ------- cos-normalize both se->sn and te->tn (grid.y selects) -------
__global__ void normscale2(const float* __restrict__ se, const float* __restrict__ te,
                           float* __restrict__ sn, float* __restrict__ tn)
{
    const float* x   = blockIdx.y ? te : se;
    float*       out = blockIdx.y ? tn : sn;
    int row = blockIdx.x * 8 + (threadIdx.x >> 5);
    int lane = threadIdx.x & 31;
    const float* p = x + (size_t)row * 128;
    float v[4];
    float s = 0.f;
    #pragma unroll
    for (int c = 0; c < 4; c++) { v[c] = p[lane + c*32]; s += v[c] * v[c]; }
    #pragma unroll
    for (int o = 16; o > 0; o >>= 1) s += __shfl_xor_sync(0xffffffff, s, o);
    float inv = 1.f / fmaxf(sqrtf(s), 1e-8f);
    float* q = out + (size_t)row * 128;
    #pragma unroll
    for (int c = 0; c < 4; c++) q[lane + c*32] = v[c] * inv;
}

// ------- M partials via tensor cores: Mpart[p,b] = sn_chunk^T @ tn_chunk -------
__global__ void macc_tc(const float* __restrict__ sn, const float* __restrict__ tn,
                        float* __restrict__ Mpart)
{
    constexpr int LDSm = 136;
    __shared__ uint32_t sns[32][LDSm], tns[32][LDSm];
    const int t = threadIdx.x;
    const int warp = t >> 5, lane = t & 31;
    const int wm = (warp >> 2) * 64, wn = (warp & 3) * 32;
    const int g = lane >> 2, tq = lane & 3;
    const size_t row0 = (size_t)blockIdx.y * SEQ + blockIdx.x * 128;

    float acc[4][4][4];
    #pragma unroll
    for (int mi = 0; mi < 4; mi++)
        #pragma unroll
        for (int ni = 0; ni < 4; ni++)
            #pragma unroll
            for (int q = 0; q < 4; q++) acc[mi][ni][q] = 0.f;

    for (int c0 = 0; c0 < 128; c0 += 32) {
        #pragma unroll
        for (int i = 0; i < 4; i++) {
            int idx = t + 256*i; int r = idx >> 5; int c4 = (idx & 31) * 4;
            float4 a = *(const float4*)&sn[(row0 + c0 + r) * 128 + c4];
            float4 b = *(const float4*)&tn[(row0 + c0 + r) * 128 + c4];
            *(float4*)&sns[r][c4] = a;
            *(float4*)&tns[r][c4] = b;
        }
        __syncthreads();
        #pragma unroll
        for (int kk = 0; kk < 32; kk += 8) {
            uint32_t af[4][4], bf[4][2];
            #pragma unroll
            for (int mi = 0; mi < 4; mi++) {
                int m = wm + mi * 16;
                af[mi][0] = rtfb(sns[kk + tq    ][m + g    ]);
                af[mi][1] = rtfb(sns[kk + tq    ][m + g + 8]);
                af[mi][2] = rtfb(sns[kk + tq + 4][m + g    ]);
                af[mi][3] = rtfb(sns[kk + tq + 4][m + g + 8]);
            }
            #pragma unroll
            for (int ni = 0; ni < 4; ni++) {
                int n = wn + ni * 8 + g;
                bf[ni][0] = rtfb(tns[kk + tq    ][n]);
                bf[ni][1] = rtfb(tns[kk + tq + 4][n]);
            }
            #pragma unroll
            for (int mi = 0; mi < 4; mi++)
                #pragma unroll
                for (int ni = 0; ni < 4; ni++)
                    mma_tf32(acc[mi][ni], af[mi], bf[ni]);
        }
        __syncthreads();
    }
    float* o = Mpart + ((size_t)blockIdx.x * BTCH + blockIdx.y) * 16384;
    #pragma unroll
    for (int mi = 0; mi < 4; mi++) {
        #pragma unroll
        for (int ni = 0; ni < 4; ni++) {
            int m = wm + mi * 16 + g;
            int nn = wn + ni * 8 + tq * 2;
            o[m*128 + nn]       = acc[mi][ni][0];
            o[m*128 + nn + 1]   = acc[mi][ni][1];
            o[(m+8)*128 + nn]   = acc[mi][ni][2];
            o[(m+8)*128 + nn+1] = acc[mi][ni][3];
        }
    }
}

__global__ void mreduce(const float* __restrict__ Mpart, float* __restrict__ M)
{
    int idx = blockIdx.x * 256 + threadIdx.x;   // 8*16384 total
    float s = 0.f;
    #pragma unroll
    for (int p = 0; p < 16; p++) s += Mpart[(size_t)p * (BTCH*128*128) + idx];
    M[idx] = s;
}

// ------- interaction attention: len=8 (batch axis), batch=S, 8 heads of 16 -------
__global__ void interattn(const float* __restrict__ qb, const float* __restrict__ kvb,
                          float* __restrict__ out)
{
    int gid = blockIdx.x * 256 + threadIdx.x;     // 2048*8*8 = 131072 threads
    int s = gid >> 6; int r = gid & 63; int h = r >> 3; int i = r & 7;
    const float* q = qb + ((size_t)i * SEQ + s) * 128 + h*16;
    float qr[16];
    #pragma unroll
    for (int d = 0; d < 16; d++) qr[d] = q[d];
    float sc[8];
    float mx = -1e30f;
    #pragma unroll
    for (int j = 0; j < 8; j++) {
        const float* k = kvb + ((size_t)j * SEQ + s) * 256 + h*16;
        float a = 0.f;
        #pragma unroll
        for (int d = 0; d < 16; d++) a += qr[d] * k[d];
        sc[j] = a * 0.25f;
        mx = fmaxf(mx, sc[j]);
    }
    float sum = 0.f;
    #pragma unroll
    for (int j = 0; j < 8; j++) { sc[j] = expf(sc[j] - mx); sum += sc[j]; }
    float inv = 1.f / sum;
    float o[16];
    #pragma unroll
    for (int d = 0; d < 16; d++) o[d] = 0.f;
    #pragma unroll
    for (int j = 0; j < 8; j++) {
        const float* v = kvb + ((size_t)j * SEQ + s) * 256 + 128 + h*16;
        float p = sc[j] * inv;
        #pragma unroll
        for (int d = 0; d < 16; d++) o[d] += p * v[d];
    }
    float* op = out + ((size_t)i * SEQ + s) * 128 + h*16;
    #pragma unroll
    for (int d = 0; d < 16; d++) op[d] = o[d];
}

// ==================================================================================
extern "C" void kernel_launch(void* const* d_in, const int* in_sizes, int n_in,
                              void* d_out, int out_size)
{
    const float* x        = (const float*)d_in[0];
    const float* spatial  = (const float*)d_in[1];
    const float* temporal = (const float*)d_in[2];
    const float* lw_in_w  = (const float*)d_in[3];
    const float* lw_in_b  = (const float*)d_in[4];
    const float* lw_out_w = (const float*)d_in[5];
    const float* lw_out_b = (const float*)d_in[6];
    const float* spat_w   = (const float*)d_in[7];
    const float* spat_b   = (const float*)d_in[8];
    const float* temp_w   = (const float*)d_in[9];
    const float* temp_b   = (const float*)d_in[10];
    const float* int_in_w = (const float*)d_in[11];
    const float* int_in_b = (const float*)d_in[12];
    const float* int_out_w= (const float*)d_in[13];
    const float* int_out_b= (const float*)d_in[14];
    const float* ffn_w1   = (const float*)d_in[15];
    const float* ffn_b1   = (const float*)d_in[16];
    const float* ffn_w2   = (const float*)d_in[17];
    const float* ffn_b2   = (const float*)d_in[18];
    const float* ln1_g    = (const float*)d_in[19];
    const float* ln1_b    = (const float*)d_in[20];
    const float* ln2_g    = (const float*)d_in[21];
    const float* ln2_b    = (const float*)d_in[22];
    float* out = (float*)d_out;

    void *p;
    cudaGetSymbolAddress(&p, g_qkv);  float* qkv  = (float*)p;
    cudaGetSymbolAddress(&p, g_attn); float* attn = (float*)p;
    cudaGetSymbolAddress(&p, g_x1);   float* x1   = (float*)p;
    cudaGetSymbolAddress(&p, g_hbuf); float* hbuf = (float*)p;
    cudaGetSymbolAddress(&p, g_x2);   float* x2   = (float*)p;
    cudaGetSymbolAddress(&p, g_se);   float* se   = (float*)p;
    cudaGetSymbolAddress(&p, g_te);   float* te   = (float*)p;
    cudaGetSymbolAddress(&p, g_sn);   float* sn   = (float*)p;
    cudaGetSymbolAddress(&p, g_tn);   float* tn   = (float*)p;
    cudaGetSymbolAddress(&p, g_Mpart);float* Mp   = (float*)p;
    cudaGetSymbolAddress(&p, g_M);    float* M    = (float*)p;
    cudaGetSymbolAddress(&p, g_sim);  float* sim  = (float*)p;
    cudaGetSymbolAddress(&p, g_qi);   float* qi   = (float*)p;
    cudaGetSymbolAddress(&p, g_kvi);  float* kvi  = (float*)p;
    cudaGetSymbolAddress(&p, g_ip);   float* ip   = (float*)p;

    const int SMEM = 2 * (128 + 128) * 36 * 4;   // 73728 (>= 4KB epilogue scratch)
    cudaFuncSetAttribute(gemm_tc2<0,false>, cudaFuncAttributeMaxDynamicSharedMemorySize, SMEM);
    cudaFuncSetAttribute(gemm_tc2<1,false>, cudaFuncAttributeMaxDynamicSharedMemorySize, SMEM);
    cudaFuncSetAttribute(gemm_tc2<2,false>, cudaFuncAttributeMaxDynamicSharedMemorySize, SMEM);
    cudaFuncSetAttribute(gemm_tc2<4,false>, cudaFuncAttributeMaxDynamicSharedMemorySize, SMEM);
    cudaFuncSetAttribute(gemm_tc2<5,true>,  cudaFuncAttributeMaxDynamicSharedMemorySize, SMEM);
    cudaFuncSetAttribute(gemm_tc2<6,false>, cudaFuncAttributeMaxDynamicSharedMemorySize, SMEM);

    cudaStream_t s0 = cudaStreamPerThread;    // the capturing / main stream
    cudaStream_t s2 = g_s2;

    // fork: bring s2 into the capture graph with a root dependency
    cudaEventRecord(g_e0, s0);
    cudaStreamWaitEvent(s2, g_e0, 0);

    // ---------- branch A (main stream): window attention + FFN ----------
    gemm_tc2<0,false><<<dim3(3,128),256,SMEM,s0>>>(x, lw_in_w, lw_in_b, qkv, 128, 384, nullptr, nullptr, nullptr, nullptr);
    winattn2<<<2048,128,0,s0>>>(qkv, attn);
    gemm_tc2<4,false><<<dim3(1,128),256,SMEM,s0>>>(attn, lw_out_w, lw_out_b, x1, 128, 128, x, nullptr, ln1_g, ln1_b);
    gemm_tc2<1,false><<<dim3(4,128),256,SMEM,s0>>>(x1, ffn_w1, ffn_b1, hbuf, 128, 512, nullptr, nullptr, nullptr, nullptr);
    gemm_tc2<4,false><<<dim3(1,128),256,SMEM,s0>>>(hbuf, ffn_w2, ffn_b2, x2, 512, 128, x1, nullptr, ln2_g, ln2_b);

    // ---------- branch B (s2): spatio-temporal similarity + interaction ----------
    // dual GEMM: z=0 -> se = spatial@spat_w^T + spat_b ; z=1 -> te = temporal@temp_w^T + temp_b
    gemm_tc2<6,false><<<dim3(1,128,2),256,SMEM,s2>>>(spatial, spat_w, spat_b, se, 128, 128,
                                                     temporal, temp_w, temp_b, (const float*)te);
    normscale2<<<dim3(NTOK/8,2),256,0,s2>>>(se, te, sn, tn);
    macc_tc<<<dim3(16,8),256,0,s2>>>(sn, tn, Mp);
    mreduce<<<(BTCH*128*128)/256,256,0,s2>>>(Mp, M);
    // sim = (sn . (M @ tn)) / SEQ, fused in-epilogue
    gemm_tc2<5,true><<<dim3(1,128),256,SMEM,s2>>>(tn, M, nullptr, sim, 128, 128, sn, nullptr, nullptr, nullptr);
    gemm_tc2<0,false><<<dim3(1,128),256,SMEM,s2>>>(se, int_in_w, int_in_b, qi, 128, 128, nullptr, nullptr, nullptr, nullptr);
    gemm_tc2<0,false><<<dim3(2,128),256,SMEM,s2>>>(te, int_in_w + 128*128, int_in_b + 128, kvi, 128, 256, nullptr, nullptr, nullptr, nullptr);
    interattn<<<512,256,0,s2>>>(qi, kvi, ip);
    cudaEventRecord(g_e1, s2);

    // ---------- join: out = x2 + sim * (ip @ int_out_w^T + int_out_b) ----------
    cudaStreamWaitEvent(s0, g_e1, 0);
    gemm_tc2<2,false><<<dim3(1,128),256,SMEM,s0>>>(ip, int_out_w, int_out_b, out, 128, 128, x2, sim, nullptr, nullptr);
}

// round 14
// speedup vs baseline: 3.8071x; 1.0248x over previous
#include <cuda_runtime.h>
#include <math.h>
#include <stdint.h>

#define BTCH 8
#define SEQ  2048
#define DIMD 128
#define NTOK (BTCH*SEQ)   /* 16384 */
#define WIN  64
#define NHEAD 8
#define HD   16
#define FFND 512

// ---------------- scratch (device globals; no runtime allocation) ----------------
__device__ float g_qkv [NTOK*384];
__device__ float g_attn[NTOK*DIMD];
__device__ float g_x1  [NTOK*DIMD];
__device__ float g_hbuf[NTOK*FFND];
__device__ float g_x2  [NTOK*DIMD];
__device__ float g_se  [NTOK*DIMD];
__device__ float g_te  [NTOK*DIMD];
__device__ float g_sn  [NTOK*DIMD];
__device__ float g_tn  [NTOK*DIMD];
__device__ float g_Mpart[8*BTCH*DIMD*DIMD];
__device__ float g_M   [BTCH*DIMD*DIMD];
__device__ float g_sim [NTOK];
__device__ float g_qi  [NTOK*DIMD];
__device__ float g_kvi [NTOK*256];
__device__ float g_ip  [NTOK*DIMD];

// ---------------- stream fork resources (created pre-main) ----------------
static cudaStream_t g_s2;
static cudaEvent_t  g_e0, g_e1;
struct StreamInit {
    StreamInit() {
        cudaStreamCreateWithFlags(&g_s2, cudaStreamNonBlocking);
        cudaEventCreateWithFlags(&g_e0, cudaEventDisableTiming);
        cudaEventCreateWithFlags(&g_e1, cudaEventDisableTiming);
    }
};
static StreamInit g_si;

// ---------------- tf32 helpers ----------------
// NOTE: mma.sync tf32 reads fp32-bit-layout operands and ignores the low 13
// mantissa bits (truncation). We feed raw fp32 bits — no cvt in the mainloop.
__device__ __forceinline__ void mma_tf32(float c[4], const uint32_t a[4], const uint32_t b[2]) {
    asm("mma.sync.aligned.m16n8k8.row.col.f32.tf32.tf32.f32 "
        "{%0,%1,%2,%3}, {%4,%5,%6,%7}, {%8,%9}, {%0,%1,%2,%3};"
        : "+f"(c[0]), "+f"(c[1]), "+f"(c[2]), "+f"(c[3])
        : "r"(a[0]), "r"(a[1]), "r"(a[2]), "r"(a[3]), "r"(b[0]), "r"(b[1]));
}
__device__ __forceinline__ void cpasync16(uint32_t saddr, const float* g) {
    asm volatile("cp.async.cg.shared.global [%0], [%1], 16;\n" :: "r"(saddr), "l"(g));
}

// -------- tensor-core GEMM (tf32, cp.async 2-stage): C = A[M,K] @ W[N,K]^T --------
// BM=128, BK=32, BN=128 (full row per block). 256 threads = 8 warps (2 x 4).
// __launch_bounds__(256,2): cap regs at 128 so 2 CTAs co-reside per SM.
// EPI: 0 bias            1 bias+GELU
//      2 resid + scale[row]*(acc+bias)            (final join)
//      4 LayerNorm(acc + bias + resid)*gam + bet  (fused ln)
//      5 sim[row] = (acc-row . snrow)/SEQ         (no bias; C=sim, resid=sn)
//      6 dual bias GEMM: blockIdx.z==1 uses (resid,scale,gam,bet) as (A2,W2,b2,C2)
// BATCHW: W advances by 128*128 per 2048 A-rows
template<int EPI, bool BATCHW>
__global__ void __launch_bounds__(256, 2)
gemm_tc2(const float* __restrict__ A, const float* __restrict__ W,
         const float* __restrict__ bias, float* __restrict__ C,
         int K, int N,
         const float* __restrict__ resid, const float* __restrict__ scale,
         const float* __restrict__ gam, const float* __restrict__ bet)
{
    constexpr int BM = 128, BK = 32, BN = 128;
    constexpr int WM = 64, WN = 32;
    constexpr int MT = 4, NT = 4;
    constexpr int LDS_ = 36;                 // bank = (4*row+col)%32 -> permutation
    constexpr int STG  = (BM + BN) * LDS_;   // words per stage

    // dual-job pointer selection (EPI==6)
    const float* A_   = A;
    const float* W_   = W;
    const float* bias_= bias;
    float*       C_   = C;
    if (EPI == 6 && blockIdx.z == 1) {
        A_ = resid; W_ = scale; bias_ = gam; C_ = (float*)bet;
    }

    extern __shared__ uint32_t sh[];
    const int t = threadIdx.x;
    const int warp = t >> 5, lane = t & 31;
    const int wrow = warp >> 2, wcol = warp & 3;
    const int wm = wrow * WM;
    const int wn = wcol * WN;
    const int g  = lane >> 2;
    const int tq = lane & 3;
    const int m0 = blockIdx.y * BM;
    const int n0 = blockIdx.x * BN;
    const float* Wb = BATCHW ? (W_ + (size_t)(blockIdx.y >> 4) * 16384) : W_;

    const uint32_t sbase = (uint32_t)__cvta_generic_to_shared(sh);
    const int lr = t >> 3;          // 0..31
    const int lc = (t & 7) * 4;     // 0..28

    auto load_stage = [&](int k0, int s) {
        uint32_t off = sbase + (uint32_t)s * STG * 4;
        #pragma unroll
        for (int i = 0; i < 4; i++) {
            int r = lr + 32 * i;
            cpasync16(off + (uint32_t)(r * LDS_ + lc) * 4, A_ + (size_t)(m0 + r) * K + k0 + lc);
        }
        uint32_t offB = off + (uint32_t)BM * LDS_ * 4;
        #pragma unroll
        for (int i = 0; i < 4; i++) {
            int r = lr + 32 * i;
            cpasync16(offB + (uint32_t)(r * LDS_ + lc) * 4, Wb + (size_t)(n0 + r) * K + k0 + lc);
        }
        asm volatile("cp.async.commit_group;\n" ::);
    };

    float acc[MT][NT][4];
    #pragma unroll
    for (int mi = 0; mi < MT; mi++)
        #pragma unroll
        for (int ni = 0; ni < NT; ni++)
            #pragma unroll
            for (int q = 0; q < 4; q++) acc[mi][ni][q] = 0.f;

    load_stage(0, 0);
    const int KT = K / BK;
    for (int kt = 0; kt < KT; kt++) {
        if (kt + 1 < KT) {
            load_stage((kt + 1) * BK, (kt + 1) & 1);
            asm volatile("cp.async.wait_group 1;\n" ::);
        } else {
            asm volatile("cp.async.wait_group 0;\n" ::);
        }
        __syncthreads();
        const uint32_t (*As)[LDS_] = (const uint32_t(*)[LDS_])(sh + (kt & 1) * STG);
        const uint32_t (*Bs)[LDS_] = (const uint32_t(*)[LDS_])(sh + (kt & 1) * STG + BM * LDS_);
        #pragma unroll
        for (int kk = 0; kk < BK; kk += 8) {
            uint32_t af[MT][4], bf[NT][2];
            #pragma unroll
            for (int mi = 0; mi < MT; mi++) {
                int mr = wm + mi * 16;
                af[mi][0] = As[mr + g    ][kk + tq    ];
                af[mi][1] = As[mr + g + 8][kk + tq    ];
                af[mi][2] = As[mr + g    ][kk + tq + 4];
                af[mi][3] = As[mr + g + 8][kk + tq + 4];
            }
            #pragma unroll
            for (int ni = 0; ni < NT; ni++) {
                int nr = wn + ni * 8;
                bf[ni][0] = Bs[nr + g][kk + tq    ];
                bf[ni][1] = Bs[nr + g][kk + tq + 4];
            }
            #pragma unroll
            for (int mi = 0; mi < MT; mi++)
                #pragma unroll
                for (int ni = 0; ni < NT; ni++)
                    mma_tf32(acc[mi][ni], af[mi], bf[ni]);
        }
        __syncthreads();
    }
    // (mainloop ends with __syncthreads -> smem reusable below)

    if (EPI == 4) {
        // ---- fused residual + LayerNorm over the full 128-col row ----
        float ps[8], pq[8];
        #pragma unroll
        for (int i = 0; i < 8; i++) { ps[i] = 0.f; pq[i] = 0.f; }
        #pragma unroll
        for (int mi = 0; mi < MT; mi++) {
            #pragma unroll
            for (int ni = 0; ni < NT; ni++) {
                int nn = wn + ni * 8 + tq * 2;
                float b0 = bias_[nn], b1 = bias_[nn + 1];
                #pragma unroll
                for (int half = 0; half < 2; half++) {
                    int lm = wm + mi * 16 + g + half * 8;
                    size_t gm = (size_t)(m0 + lm);
                    float v0 = acc[mi][ni][half*2+0] + b0 + resid[gm*128 + nn];
                    float v1 = acc[mi][ni][half*2+1] + b1 + resid[gm*128 + nn + 1];
                    acc[mi][ni][half*2+0] = v0;
                    acc[mi][ni][half*2+1] = v1;
                    int ri = mi*2 + half;
                    ps[ri] += v0 + v1;
                    pq[ri] += v0*v0 + v1*v1;
                }
            }
        }
        #pragma unroll
        for (int off = 1; off <= 2; off <<= 1)
            #pragma unroll
            for (int i = 0; i < 8; i++) {
                ps[i] += __shfl_xor_sync(0xffffffff, ps[i], off);
                pq[i] += __shfl_xor_sync(0xffffffff, pq[i], off);
            }
        float* rs = (float*)sh;        // [128][4]
        float* rq = rs + 512;
        if (tq == 0) {
            #pragma unroll
            for (int i = 0; i < 8; i++) {
                int lm = wm + (i >> 1) * 16 + g + (i & 1) * 8;
                rs[lm*4 + wcol] = ps[i];
                rq[lm*4 + wcol] = pq[i];
            }
        }
        __syncthreads();
        #pragma unroll
        for (int mi = 0; mi < MT; mi++) {
            #pragma unroll
            for (int half = 0; half < 2; half++) {
                int lm = wm + mi * 16 + g + half * 8;
                float su = rs[lm*4+0] + rs[lm*4+1] + rs[lm*4+2] + rs[lm*4+3];
                float sq = rq[lm*4+0] + rq[lm*4+1] + rq[lm*4+2] + rq[lm*4+3];
                float mu = su * (1.f/128.f);
                float var = sq * (1.f/128.f) - mu*mu;
                float rstd = rsqrtf(var + 1e-5f);
                size_t gm = (size_t)(m0 + lm);
                #pragma unroll
                for (int ni = 0; ni < NT; ni++) {
                    int nn = wn + ni * 8 + tq * 2;
                    float o0 = (acc[mi][ni][half*2+0] - mu) * rstd * gam[nn]   + bet[nn];
                    float o1 = (acc[mi][ni][half*2+1] - mu) * rstd * gam[nn+1] + bet[nn+1];
                    *(float2*)&C_[gm*128 + nn] = make_float2(o0, o1);
                }
            }
        }
        return;
    }

    if (EPI == 5) {
        // ---- sim[row] = (acc_row . sn_row) / SEQ ; resid == sn, C == sim ----
        float ps[8];
        #pragma unroll
        for (int i = 0; i < 8; i++) ps[i] = 0.f;
        #pragma unroll
        for (int mi = 0; mi < MT; mi++) {
            #pragma unroll
            for (int ni = 0; ni < NT; ni++) {
                int nn = wn + ni * 8 + tq * 2;
                #pragma unroll
                for (int half = 0; half < 2; half++) {
                    int lm = wm + mi * 16 + g + half * 8;
                    size_t gm = (size_t)(m0 + lm);
                    ps[mi*2+half] += acc[mi][ni][half*2+0] * resid[gm*128 + nn]
                                   + acc[mi][ni][half*2+1] * resid[gm*128 + nn + 1];
                }
            }
        }
        #pragma unroll
        for (int off = 1; off <= 2; off <<= 1)
            #pragma unroll
            for (int i = 0; i < 8; i++)
                ps[i] += __shfl_xor_sync(0xffffffff, ps[i], off);
        float* rs = (float*)sh;        // [128][4]
        if (tq == 0) {
            #pragma unroll
            for (int i = 0; i < 8; i++) {
                int lm = wm + (i >> 1) * 16 + g + (i & 1) * 8;
                rs[lm*4 + wcol] = ps[i];
            }
        }
        __syncthreads();
        if (wcol == 0 && tq == 0) {
            #pragma unroll
            for (int i = 0; i < 8; i++) {
                int lm = wm + (i >> 1) * 16 + g + (i & 1) * 8;
                float su = rs[lm*4+0] + rs[lm*4+1] + rs[lm*4+2] + rs[lm*4+3];
                C_[m0 + lm] = su * (1.f / (float)SEQ);
            }
        }
        return;
    }

    #pragma unroll
    for (int mi = 0; mi < MT; mi++) {
        #pragma unroll
        for (int ni = 0; ni < NT; ni++) {
            int m = m0 + wm + mi * 16 + g;
            int nn = n0 + wn + ni * 8 + tq * 2;
            float b0 = bias_[nn], b1 = bias_[nn + 1];
            #pragma unroll
            for (int half = 0; half < 2; half++) {
                int mm = m + half * 8;
                float v0 = acc[mi][ni][half*2 + 0] + b0;
                float v1 = acc[mi][ni][half*2 + 1] + b1;
                if (EPI == 1) {
                    v0 = 0.5f * v0 * (1.f + erff(v0 * 0.70710678118654752f));
                    v1 = 0.5f * v1 * (1.f + erff(v1 * 0.70710678118654752f));
                }
                if (EPI == 2) {
                    float sc = scale[mm];
                    v0 = resid[(size_t)mm * N + nn    ] + sc * v0;
                    v1 = resid[(size_t)mm * N + nn + 1] + sc * v1;
                }
                *(float2*)&C_[(size_t)mm * N + nn] = make_float2(v0, v1);
            }
        }
    }
}

// ------- local-window causal attention: one block per (window, head) -------
__global__ void winattn2(const float* __restrict__ qkv, float* __restrict__ out)
{
    __shared__ float qs[WIN][17], ks[WIN][17], vs[WIN][17], sc[WIN][65];
    const int w = blockIdx.x >> 3, h = blockIdx.x & 7;
    const int base = w * WIN;
    const int t = threadIdx.x;   // 128
    #pragma unroll
    for (int i = 0; i < 8; i++) {
        int idx = t + 128*i; int r = idx >> 4, c = idx & 15;
        size_t rb = (size_t)(base + r) * 384 + h*16 + c;
        qs[r][c] = qkv[rb];
        ks[r][c] = qkv[rb + 128];
        vs[r][c] = qkv[rb + 256];
    }
    __syncthreads();
    #pragma unroll
    for (int i = 0; i < 32; i++) {
        int idx = t + 128*i; int row = idx >> 6, j = idx & 63;
        float s = 0.f;
        #pragma unroll
        for (int d = 0; d < 16; d++) s += qs[row][d] * ks[j][d];
        sc[row][j] = s * 0.25f;
    }
    __syncthreads();
    if (t < 64) {
        int i = t;
        float mx = -1e30f;
        for (int j = 0; j <= i; j++) mx = fmaxf(mx, sc[i][j]);
        float sum = 0.f;
        for (int j = 0; j <= i; j++) { float p = expf(sc[i][j] - mx); sc[i][j] = p; sum += p; }
        float inv = 1.f / sum;
        for (int j = 0; j <= i; j++) sc[i][j] *= inv;
        for (int j = i + 1; j < 64; j++) sc[i][j] = 0.f;
    }
    __syncthreads();
    #pragma unroll
    for (int i2 = 0; i2 < 8; i2++) {
        int idx = t + 128*i2; int i = idx >> 4, d = idx & 15;
        float s = 0.f;
        for (int j = 0; j < 64; j++) s += sc[i][j] * vs[j][d];
        out[(size_t)(base + i) * 128 + h*16 + d] = s;
    }
}

// ------- cos-normalize both se->sn and te->tn (grid.y selects) -------
__global__ void normscale2(const float* __restrict__ se, const float* __restrict__ te,
                           float* __restrict__ sn, float* __restrict__ tn)
{
    const float* x   = blockIdx.y ? te : se;
    float*       out = blockIdx.y ? tn : sn;
    int row = blockIdx.x * 8 + (threadIdx.x >> 5);
    int lane = threadIdx.x & 31;
    const float* p = x + (size_t)row * 128;
    float v[4];
    float s = 0.f;
    #pragma unroll
    for (int c = 0; c < 4; c++) { v[c] = p[lane + c*32]; s += v[c] * v[c]; }
    #pragma unroll
    for (int o = 16; o > 0; o >>= 1) s += __shfl_xor_sync(0xffffffff, s, o);
    float inv = 1.f / fmaxf(sqrtf(s), 1e-8f);
    float* q = out + (size_t)row * 128;
    #pragma unroll
    for (int c = 0; c < 4; c++) q[lane + c*32] = v[c] * inv;
}

// ------- M partials via tensor cores: Mpart[p,b] = sn_chunk^T @ tn_chunk -------
// grid (8, 8): each block accumulates 256 rows (8 x 32-row tiles).
__global__ void macc_tc(const float* __restrict__ sn, const float* __restrict__ tn,
                        float* __restrict__ Mpart)
{
    constexpr int LDSm = 136;
    __shared__ uint32_t sns[32][LDSm], tns[32][LDSm];
    const int t = threadIdx.x;
    const int warp = t >> 5, lane = t & 31;
    const int wm = (warp >> 2) * 64, wn = (warp & 3) * 32;
    const int g = lane >> 2, tq = lane & 3;
    const size_t row0 = (size_t)blockIdx.y * SEQ + blockIdx.x * 256;

    float acc[4][4][4];
    #pragma unroll
    for (int mi = 0; mi < 4; mi++)
        #pragma unroll
        for (int ni = 0; ni < 4; ni++)
            #pragma unroll
            for (int q = 0; q < 4; q++) acc[mi][ni][q] = 0.f;

    for (int c0 = 0; c0 < 256; c0 += 32) {
        #pragma unroll
        for (int i = 0; i < 4; i++) {
            int idx = t + 256*i; int r = idx >> 5; int c4 = (idx & 31) * 4;
            float4 a = *(const float4*)&sn[(row0 + c0 + r) * 128 + c4];
            float4 b = *(const float4*)&tn[(row0 + c0 + r) * 128 + c4];
            *(float4*)&sns[r][c4] = a;
            *(float4*)&tns[r][c4] = b;
        }
        __syncthreads();
        #pragma unroll
        for (int kk = 0; kk < 32; kk += 8) {
            uint32_t af[4][4], bf[4][2];
            #pragma unroll
            for (int mi = 0; mi < 4; mi++) {
                int m = wm + mi * 16;
                af[mi][0] = sns[kk + tq    ][m + g    ];
                af[mi][1] = sns[kk + tq    ][m + g + 8];
                af[mi][2] = sns[kk + tq + 4][m + g    ];
                af[mi][3] = sns[kk + tq + 4][m + g + 8];
            }
            #pragma unroll
            for (int ni = 0; ni < 4; ni++) {
                int n = wn + ni * 8 + g;
                bf[ni][0] = tns[kk + tq    ][n];
                bf[ni][1] = tns[kk + tq + 4][n];
            }
            #pragma unroll
            for (int mi = 0; mi < 4; mi++)
                #pragma unroll
                for (int ni = 0; ni < 4; ni++)
                    mma_tf32(acc[mi][ni], af[mi], bf[ni]);
        }
        __syncthreads();
    }
    float* o = Mpart + ((size_t)blockIdx.x * BTCH + blockIdx.y) * 16384;
    #pragma unroll
    for (int mi = 0; mi < 4; mi++) {
        #pragma unroll
        for (int ni = 0; ni < 4; ni++) {
            int m = wm + mi * 16 + g;
            int nn = wn + ni * 8 + tq * 2;
            o[m*128 + nn]       = acc[mi][ni][0];
            o[m*128 + nn + 1]   = acc[mi][ni][1];
            o[(m+8)*128 + nn]   = acc[mi][ni][2];
            o[(m+8)*128 + nn+1] = acc[mi][ni][3];
        }
    }
}

__global__ void mreduce(const float* __restrict__ Mpart, float* __restrict__ M)
{
    int idx = blockIdx.x * 256 + threadIdx.x;   // 8*16384 total
    float s = 0.f;
    #pragma unroll
    for (int p = 0; p < 8; p++) s += Mpart[(size_t)p * (BTCH*128*128) + idx];
    M[idx] = s;
}

// ------- interaction attention: len=8 (batch axis), batch=S, 8 heads of 16 -------
__global__ void interattn(const float* __restrict__ qb, const float* __restrict__ kvb,
                          float* __restrict__ out)
{
    int gid = blockIdx.x * 256 + threadIdx.x;     // 2048*8*8 = 131072 threads
    int s = gid >> 6; int r = gid & 63; int h = r >> 3; int i = r & 7;
    const float* q = qb + ((size_t)i * SEQ + s) * 128 + h*16;
    float qr[16];
    #pragma unroll
    for (int d = 0; d < 16; d++) qr[d] = q[d];
    float sc[8];
    float mx = -1e30f;
    #pragma unroll
    for (int j = 0; j < 8; j++) {
        const float* k = kvb + ((size_t)j * SEQ + s) * 256 + h*16;
        float a = 0.f;
        #pragma unroll
        for (int d = 0; d < 16; d++) a += qr[d] * k[d];
        sc[j] = a * 0.25f;
        mx = fmaxf(mx, sc[j]);
    }
    float sum = 0.f;
    #pragma unroll
    for (int j = 0; j < 8; j++) { sc[j] = expf(sc[j] - mx); sum += sc[j]; }
    float inv = 1.f / sum;
    float o[16];
    #pragma unroll
    for (int d = 0; d < 16; d++) o[d] = 0.f;
    #pragma unroll
    for (int j = 0; j < 8; j++) {
        const float* v = kvb + ((size_t)j * SEQ + s) * 256 + 128 + h*16;
        float p = sc[j] * inv;
        #pragma unroll
        for (int d = 0; d < 16; d++) o[d] += p * v[d];
    }
    float* op = out + ((size_t)i * SEQ + s) * 128 + h*16;
    #pragma unroll
    for (int d = 0; d < 16; d++) op[d] = o[d];
}

// ==================================================================================
extern "C" void kernel_launch(void* const* d_in, const int* in_sizes, int n_in,
                              void* d_out, int out_size)
{
    const float* x        = (const float*)d_in[0];
    const float* spatial  = (const float*)d_in[1];
    const float* temporal = (const float*)d_in[2];
    const float* lw_in_w  = (const float*)d_in[3];
    const float* lw_in_b  = (const float*)d_in[4];
    const float* lw_out_w = (const float*)d_in[5];
    const float* lw_out_b = (const float*)d_in[6];
    const float* spat_w   = (const float*)d_in[7];
    const float* spat_b   = (const float*)d_in[8];
    const float* temp_w   = (const float*)d_in[9];
    const float* temp_b   = (const float*)d_in[10];
    const float* int_in_w = (const float*)d_in[11];
    const float* int_in_b = (const float*)d_in[12];
    const float* int_out_w= (const float*)d_in[13];
    const float* int_out_b= (const float*)d_in[14];
    const float* ffn_w1   = (const float*)d_in[15];
    const float* ffn_b1   = (const float*)d_in[16];
    const float* ffn_w2   = (const float*)d_in[17];
    const float* ffn_b2   = (const float*)d_in[18];
    const float* ln1_g    = (const float*)d_in[19];
    const float* ln1_b    = (const float*)d_in[20];
    const float* ln2_g    = (const float*)d_in[21];
    const float* ln2_b    = (const float*)d_in[22];
    float* out = (float*)d_out;

    void *p;
    cudaGetSymbolAddress(&p, g_qkv);  float* qkv  = (float*)p;
    cudaGetSymbolAddress(&p, g_attn); float* attn = (float*)p;
    cudaGetSymbolAddress(&p, g_x1);   float* x1   = (float*)p;
    cudaGetSymbolAddress(&p, g_hbuf); float* hbuf = (float*)p;
    cudaGetSymbolAddress(&p, g_x2);   float* x2   = (float*)p;
    cudaGetSymbolAddress(&p, g_se);   float* se   = (float*)p;
    cudaGetSymbolAddress(&p, g_te);   float* te   = (float*)p;
    cudaGetSymbolAddress(&p, g_sn);   float* sn   = (float*)p;
    cudaGetSymbolAddress(&p, g_tn);   float* tn   = (float*)p;
    cudaGetSymbolAddress(&p, g_Mpart);float* Mp   = (float*)p;
    cudaGetSymbolAddress(&p, g_M);    float* M    = (float*)p;
    cudaGetSymbolAddress(&p, g_sim);  float* sim  = (float*)p;
    cudaGetSymbolAddress(&p, g_qi);   float* qi   = (float*)p;
    cudaGetSymbolAddress(&p, g_kvi);  float* kvi  = (float*)p;
    cudaGetSymbolAddress(&p, g_ip);   float* ip   = (float*)p;

    const int SMEM = 2 * (128 + 128) * 36 * 4;   // 73728 (>= 4KB epilogue scratch)
    cudaFuncSetAttribute(gemm_tc2<0,false>, cudaFuncAttributeMaxDynamicSharedMemorySize, SMEM);
    cudaFuncSetAttribute(gemm_tc2<1,false>, cudaFuncAttributeMaxDynamicSharedMemorySize, SMEM);
    cudaFuncSetAttribute(gemm_tc2<2,false>, cudaFuncAttributeMaxDynamicSharedMemorySize, SMEM);
    cudaFuncSetAttribute(gemm_tc2<4,false>, cudaFuncAttributeMaxDynamicSharedMemorySize, SMEM);
    cudaFuncSetAttribute(gemm_tc2<5,true>,  cudaFuncAttributeMaxDynamicSharedMemorySize, SMEM);
    cudaFuncSetAttribute(gemm_tc2<6,false>, cudaFuncAttributeMaxDynamicSharedMemorySize, SMEM);

    cudaStream_t s0 = cudaStreamPerThread;    // the capturing / main stream
    cudaStream_t s2 = g_s2;

    // fork: bring s2 into the capture graph with a root dependency
    cudaEventRecord(g_e0, s0);
    cudaStreamWaitEvent(s2, g_e0, 0);

    // ---------- branch A (main stream): window attention + FFN ----------
    gemm_tc2<0,false><<<dim3(3,128),256,SMEM,s0>>>(x, lw_in_w, lw_in_b, qkv, 128, 384, nullptr, nullptr, nullptr, nullptr);
    winattn2<<<2048,128,0,s0>>>(qkv, attn);
    gemm_tc2<4,false><<<dim3(1,128),256,SMEM,s0>>>(attn, lw_out_w, lw_out_b, x1, 128, 128, x, nullptr, ln1_g, ln1_b);
    gemm_tc2<1,false><<<dim3(4,128),256,SMEM,s0>>>(x1, ffn_w1, ffn_b1, hbuf, 128, 512, nullptr, nullptr, nullptr, nullptr);
    gemm_tc2<4,false><<<dim3(1,128),256,SMEM,s0>>>(hbuf, ffn_w2, ffn_b2, x2, 512, 128, x1, nullptr, ln2_g, ln2_b);

    // ---------- branch B (s2): spatio-temporal similarity + interaction ----------
    // dual GEMM: z=0 -> se = spatial@spat_w^T + spat_b ; z=1 -> te = temporal@temp_w^T + temp_b
    gemm_tc2<6,false><<<dim3(1,128,2),256,SMEM,s2>>>(spatial, spat_w, spat_b, se, 128, 128,
                                                     temporal, temp_w, temp_b, (const float*)te);
    normscale2<<<dim3(NTOK/8,2),256,0,s2>>>(se, te, sn, tn);
    macc_tc<<<dim3(8,8),256,0,s2>>>(sn, tn, Mp);
    mreduce<<<(BTCH*128*128)/256,256,0,s2>>>(Mp, M);
    // sim = (sn . (M @ tn)) / SEQ, fused in-epilogue
    gemm_tc2<5,true><<<dim3(1,128),256,SMEM,s2>>>(tn, M, nullptr, sim, 128, 128, sn, nullptr, nullptr, nullptr);
    gemm_tc2<0,false><<<dim3(1,128),256,SMEM,s2>>>(se, int_in_w, int_in_b, qi, 128, 128, nullptr, nullptr, nullptr, nullptr);
    gemm_tc2<0,false><<<dim3(2,128),256,SMEM,s2>>>(te, int_in_w + 128*128, int_in_b + 128, kvi, 128, 256, nullptr, nullptr, nullptr, nullptr);
    interattn<<<512,256,0,s2>>>(qi, kvi, ip);
    cudaEventRecord(g_e1, s2);

    // ---------- join: out = x2 + sim * (ip @ int_out_w^T + int_out_b) ----------
    cudaStreamWaitEvent(s0, g_e1, 0);
    gemm_tc2<2,false><<<dim3(1,128),256,SMEM,s0>>>(ip, int_out_w, int_out_b, out, 128, 128, x2, sim, nullptr, nullptr);
}